// round 7
// baseline (speedup 1.0000x reference)
#include <cuda_runtime.h>
#include <cuda_bf16.h>
#include <cstdint>
#include <math.h>

// Problem constants
#define NTOK 2048
#define HID 2048
#define NH 32
#define NKV 8
#define HD 64
#define NE 4
#define CHUNK (NTOK / NE)   // 512
#define DQ (NH * HD)        // 2048
#define DKV (NKV * HD)      // 512
#define DKV2 (2 * DKV)      // 1024

typedef __nv_bfloat16 bf16;

// Scratch
__device__ bf16 g_hh[(size_t)NTOK * HID];
__device__ bf16 g_hl[(size_t)NTOK * HID];
__device__ bf16 g_oh[(size_t)NTOK * DQ];
__device__ bf16 g_ol[(size_t)NTOK * DQ];

__device__ bf16 g_qh[(size_t)NTOK * DQ];
__device__ bf16 g_ql[(size_t)NTOK * DQ];
__device__ bf16 g_kh2[(size_t)NTOK * DKV];
__device__ bf16 g_kl2[(size_t)NTOK * DKV];
__device__ bf16 g_vh[(size_t)NTOK * DKV];
__device__ bf16 g_vl[(size_t)NTOK * DKV];

__device__ bf16 g_wq_h[(size_t)NE * HID * DQ];
__device__ bf16 g_wq_l[(size_t)NE * HID * DQ];
__device__ bf16 g_wo_h[(size_t)NE * DQ * HID];
__device__ bf16 g_wo_l[(size_t)NE * DQ * HID];
__device__ bf16 g_wkv_h[(size_t)DKV2 * HID];
__device__ bf16 g_wkv_l[(size_t)DKV2 * HID];

// ---------------------------------------------------------------------------
__device__ __forceinline__ uint32_t smem_u32(const void* p) {
    uint32_t a;
    asm("{ .reg .u64 t; cvta.to.shared.u64 t, %1; cvt.u32.u64 %0, t; }"
        : "=r"(a) : "l"(p));
    return a;
}

#define CP16(dst, src) \
    asm volatile("cp.async.cg.shared.global [%0], [%1], 16;" \
        :: "r"(dst), "l"(src) : "memory")
#define CP_COMMIT() asm volatile("cp.async.commit_group;" ::: "memory")

#define MMA16816(d, a, b0, b1) \
    asm volatile("mma.sync.aligned.m16n8k16.row.col.f32.bf16.bf16.f32 " \
        "{%0,%1,%2,%3}, {%4,%5,%6,%7}, {%8,%9}, {%0,%1,%2,%3};" \
        : "+f"((d)[0]), "+f"((d)[1]), "+f"((d)[2]), "+f"((d)[3]) \
        : "r"((a)[0]), "r"((a)[1]), "r"((a)[2]), "r"((a)[3]), "r"(b0), "r"(b1))

#define LDSM_4(r0, r1, r2, r3, a) \
    asm volatile("ldmatrix.sync.aligned.m8n8.x4.shared.b16 {%0,%1,%2,%3}, [%4];" \
        : "=r"(r0), "=r"(r1), "=r"(r2), "=r"(r3) : "r"(a))

#define LDSM_T4(r0, r1, r2, r3, a) \
    asm volatile("ldmatrix.sync.aligned.m8n8.x4.trans.shared.b16 {%0,%1,%2,%3}, [%4];" \
        : "=r"(r0), "=r"(r1), "=r"(r2), "=r"(r3) : "r"(a))

__device__ __forceinline__ void bf_split(float f, bf16& h, bf16& l) {
    h = __float2bfloat16(f);
    l = __float2bfloat16(f - __bfloat162float(h));
}

__device__ __forceinline__ void splitpack2(float a, float b, uint32_t& hi, uint32_t& lo) {
    bf16 ha, la, hb, lb;
    bf_split(a, ha, la);
    bf_split(b, hb, lb);
    hi = ((uint32_t)__bfloat16_as_ushort(hb) << 16) | __bfloat16_as_ushort(ha);
    lo = ((uint32_t)__bfloat16_as_ushort(lb) << 16) | __bfloat16_as_ushort(la);
}

// ---------------------------------------------------------------------------
// Fused input prep: 4 weight transposes + activation split, one launch.
// ---------------------------------------------------------------------------
__device__ __forceinline__ void transpose_body(
    const float* __restrict__ Wp, bf16* __restrict__ Hp, bf16* __restrict__ Lp,
    int R, int C, int bx, int by, int tid, float* tsh)
{
    int tx = tid & 31, ty = tid >> 5;
    int x = bx * 32 + tx;
    int y = by * 32 + ty;
#pragma unroll
    for (int i = 0; i < 32; i += 8)
        tsh[(ty + i) * 33 + tx] = Wp[(size_t)(y + i) * C + x];
    __syncthreads();
    int r2 = by * 32 + tx;
    int c2 = bx * 32 + ty;
#pragma unroll
    for (int i = 0; i < 32; i += 8) {
        float v = tsh[tx * 33 + (ty + i)];
        bf16 h, l;
        bf_split(v, h, l);
        Hp[(size_t)(c2 + i) * R + r2] = h;
        Lp[(size_t)(c2 + i) * R + r2] = l;
    }
}

__global__ void __launch_bounds__(256) prep_inputs(
    const float* __restrict__ q_proj_w, const float* __restrict__ o_proj_w,
    const float* __restrict__ k_w, const float* __restrict__ v_w,
    const float* __restrict__ hidden,
    bf16* __restrict__ wqh, bf16* __restrict__ wql,
    bf16* __restrict__ woh, bf16* __restrict__ wol,
    bf16* __restrict__ wkvh, bf16* __restrict__ wkvl,
    bf16* __restrict__ hh, bf16* __restrict__ hl)
{
    __shared__ float tsh[32 * 33];
    int b = blockIdx.x;
    int tid = threadIdx.x;

    if (b < 16384) {
        int bz = b >> 12, rem = b & 4095;
        int bx = rem & 63, by = rem >> 6;
        transpose_body(q_proj_w + (size_t)bz * HID * DQ,
                       wqh + (size_t)bz * HID * DQ, wql + (size_t)bz * HID * DQ,
                       HID, DQ, bx, by, tid, tsh);
    } else if (b < 32768) {
        int bb = b - 16384;
        int bz = bb >> 12, rem = bb & 4095;
        int bx = rem & 63, by = rem >> 6;
        transpose_body(o_proj_w + (size_t)bz * DQ * HID,
                       woh + (size_t)bz * DQ * HID, wol + (size_t)bz * DQ * HID,
                       DQ, HID, bx, by, tid, tsh);
    } else if (b < 33792) {
        int bb = b - 32768;
        int bx = bb & 15, by = bb >> 4;
        transpose_body(k_w, wkvh, wkvl, HID, DKV, bx, by, tid, tsh);
    } else if (b < 34816) {
        int bb = b - 33792;
        int bx = bb & 15, by = bb >> 4;
        transpose_body(v_w, wkvh + (size_t)DKV * HID, wkvl + (size_t)DKV * HID,
                       HID, DKV, bx, by, tid, tsh);
    } else {
        int i = (b - 34816) * 256 + tid;
        float4 v = reinterpret_cast<const float4*>(hidden)[i];
        bf16 h[4], l[4];
        bf_split(v.x, h[0], l[0]); bf_split(v.y, h[1], l[1]);
        bf_split(v.z, h[2], l[2]); bf_split(v.w, h[3], l[3]);
        reinterpret_cast<uint2*>(hh)[i] = *reinterpret_cast<uint2*>(h);
        reinterpret_cast<uint2*>(hl)[i] = *reinterpret_cast<uint2*>(l);
    }
}

// ---------------------------------------------------------------------------
// bf16x3 mma.sync GEMM mainloop (128x128 tile).
// ---------------------------------------------------------------------------
#define LDT 40
#define OPE (128 * LDT)
#define STAGE_E (4 * OPE)
#define GEMM_SMEM (1024 + 2 * STAGE_E * 2)

__device__ __forceinline__ void issue_tile(
    uint32_t sB, int s, int kb,
    const bf16* __restrict__ Agh, const bf16* __restrict__ Agl,
    const bf16* __restrict__ Bgh, const bf16* __restrict__ Bgl,
    const int* __restrict__ rows, int n0, int K, int tid)
{
#pragma unroll
    for (int rep = 0; rep < 2; rep++) {
        int f = tid + rep * 256;
        int m = f >> 2;
        int q = f & 3;
        uint32_t doff = sB + (uint32_t)s * (STAGE_E * 2) + m * (LDT * 2) + q * 16;
        size_t asrc = (size_t)rows[m] * K + kb + q * 8;
        size_t bsrc = (size_t)(n0 + m) * K + kb + q * 8;
        CP16(doff,           Agh + asrc);
        CP16(doff + OPE * 2, Agl + asrc);
        CP16(doff + OPE * 4, Bgh + bsrc);
        CP16(doff + OPE * 6, Bgl + bsrc);
    }
}

__device__ __forceinline__ void gemm_mainloop(
    const bf16* __restrict__ Agh, const bf16* __restrict__ Agl,
    const bf16* __restrict__ Bh_g, const bf16* __restrict__ Bl_g,
    const int* __restrict__ idx,
    int K, int m0, int n0, int zchunk, char* smc,
    float acc[2][8][4])
{
    int* rows = (int*)smc;
    const uint32_t sB = smem_u32(smc + 1024);
    const int tid = threadIdx.x;
    const int wid = tid >> 5;
    const int lane = tid & 31;

    if (tid < 128) {
        int lr = zchunk + m0 + tid;
        rows[tid] = idx ? idx[lr] : lr;
    }
    __syncthreads();

    const int wm = (wid & 3) * 32;
    const int wn = (wid >> 2) * 64;
    const uint32_t lnA = ((((lane >> 3) & 1) * 8 + (lane & 7)) * LDT + (lane >> 4) * 8) * 2;
    const uint32_t lnB = (((lane >> 4) * 8 + (lane & 7)) * LDT + ((lane >> 3) & 1) * 8) * 2;

#pragma unroll
    for (int a = 0; a < 2; a++)
#pragma unroll
        for (int b = 0; b < 8; b++)
#pragma unroll
            for (int c = 0; c < 4; c++) acc[a][b][c] = 0.f;

    const int nkt = K / 32;
    issue_tile(sB, 0, 0, Agh, Agl, Bh_g, Bl_g, rows, n0, K, tid); CP_COMMIT();
    issue_tile(sB, 1, 32, Agh, Agl, Bh_g, Bl_g, rows, n0, K, tid); CP_COMMIT();

    for (int kt = 0; kt < nkt; kt++) {
        if (kt + 1 < nkt) asm volatile("cp.async.wait_group 1;" ::: "memory");
        else              asm volatile("cp.async.wait_group 0;" ::: "memory");
        __syncthreads();

        const int s = kt & 1;
        const uint32_t sb_s = sB + (uint32_t)s * (STAGE_E * 2);

#pragma unroll
        for (int ks = 0; ks < 32; ks += 16) {
            uint32_t ah[2][4], al[2][4];
            uint32_t abase = sb_s + (uint32_t)(wm * LDT + ks) * 2 + lnA;
#pragma unroll
            for (int mi = 0; mi < 2; mi++) {
                LDSM_4(ah[mi][0], ah[mi][1], ah[mi][2], ah[mi][3],
                       abase + mi * (16 * LDT * 2));
                LDSM_4(al[mi][0], al[mi][1], al[mi][2], al[mi][3],
                       abase + mi * (16 * LDT * 2) + OPE * 2);
            }
#pragma unroll
            for (int np = 0; np < 4; np++) {
                uint32_t boff = sb_s + OPE * 4
                              + (uint32_t)((wn + np * 16) * LDT + ks) * 2 + lnB;
                uint32_t bh0, bh1, bh2, bh3, bl0, bl1, bl2, bl3;
                LDSM_4(bh0, bh1, bh2, bh3, boff);
                LDSM_4(bl0, bl1, bl2, bl3, boff + OPE * 2);
#pragma unroll
                for (int mi = 0; mi < 2; mi++) {
                    MMA16816(acc[mi][2 * np], ah[mi], bh0, bh1);
                    MMA16816(acc[mi][2 * np], ah[mi], bl0, bl1);
                    MMA16816(acc[mi][2 * np], al[mi], bh0, bh1);
                    MMA16816(acc[mi][2 * np + 1], ah[mi], bh2, bh3);
                    MMA16816(acc[mi][2 * np + 1], ah[mi], bl2, bl3);
                    MMA16816(acc[mi][2 * np + 1], al[mi], bh2, bh3);
                }
            }
        }
        __syncthreads();
        if (kt + 2 < nkt) {
            issue_tile(sB, s, (kt + 2) * 32, Agh, Agl, Bh_g, Bl_g, rows, n0, K, tid);
            CP_COMMIT();
        }
    }
}

// Epilogue: fused RMSNorm + NeoX RoPE + bf16 split (warp tile = one head)
__device__ __forceinline__ void epi_norm_rope(
    float acc[2][8][4], const int* __restrict__ rows,
    const float* __restrict__ w, const int* __restrict__ pos, float sc,
    bf16* __restrict__ Hi, bf16* __restrict__ Lo, int outstride, int headcol0)
{
    const int lane = threadIdx.x & 31;
    const int wid = threadIdx.x >> 5;
    const int wm = (wid & 3) * 32;
    const int rq = lane >> 2, cq = lane & 3;

#pragma unroll
    for (int mi = 0; mi < 2; mi++) {
#pragma unroll
        for (int hf = 0; hf < 2; hf++) {
            int r = wm + mi * 16 + rq + hf * 8;
            int gr = rows[r];
            float ss = 0.f;
#pragma unroll
            for (int nf = 0; nf < 8; nf++) {
                float a = acc[mi][nf][hf * 2], b = acc[mi][nf][hf * 2 + 1];
                ss += a * a + b * b;
            }
            ss += __shfl_xor_sync(0xffffffff, ss, 1);
            ss += __shfl_xor_sync(0xffffffff, ss, 2);
            float rn = rsqrtf(ss * (1.0f / 64.0f) + 1e-6f) * sc;
            float p = (float)pos[gr];
#pragma unroll
            for (int nf = 0; nf < 4; nf++) {
                float o1[2], o2[2];
#pragma unroll
                for (int par = 0; par < 2; par++) {
                    int c = nf * 8 + cq * 2 + par;
                    float y1 = acc[mi][nf][hf * 2 + par] * rn * w[c];
                    float y2 = acc[mi][nf + 4][hf * 2 + par] * rn * w[c + 32];
                    float inv = powf(10000.0f, -(float)c * (1.0f / 32.0f));
                    float sn, cs;
                    sincosf(p * inv, &sn, &cs);
                    o1[par] = y1 * cs - y2 * sn;
                    o2[par] = y2 * cs + y1 * sn;
                }
                uint32_t ph, pl;
                size_t base = (size_t)gr * outstride + headcol0 + nf * 8 + cq * 2;
                splitpack2(o1[0], o1[1], ph, pl);
                *reinterpret_cast<uint32_t*>(Hi + base) = ph;
                *reinterpret_cast<uint32_t*>(Lo + base) = pl;
                splitpack2(o2[0], o2[1], ph, pl);
                *reinterpret_cast<uint32_t*>(Hi + base + 32) = ph;
                *reinterpret_cast<uint32_t*>(Lo + base + 32) = pl;
            }
        }
    }
}

// Epilogue: plain bf16 split (v)
__device__ __forceinline__ void epi_split(
    float acc[2][8][4], const int* __restrict__ rows,
    bf16* __restrict__ Hi, bf16* __restrict__ Lo, int outstride, int col0)
{
    const int lane = threadIdx.x & 31;
    const int wid = threadIdx.x >> 5;
    const int wm = (wid & 3) * 32;
    const int wn = (wid >> 2) * 64;
    const int rq = lane >> 2, cq = lane & 3;
#pragma unroll
    for (int mi = 0; mi < 2; mi++) {
        int r = wm + mi * 16 + rq;
        size_t gr0 = (size_t)rows[r];
        size_t gr1 = (size_t)rows[r + 8];
#pragma unroll
        for (int nf = 0; nf < 8; nf++) {
            int col = col0 + wn + nf * 8 + cq * 2;
            uint32_t ph, pl;
            splitpack2(acc[mi][nf][0], acc[mi][nf][1], ph, pl);
            *reinterpret_cast<uint32_t*>(Hi + gr0 * outstride + col) = ph;
            *reinterpret_cast<uint32_t*>(Lo + gr0 * outstride + col) = pl;
            splitpack2(acc[mi][nf][2], acc[mi][nf][3], ph, pl);
            *reinterpret_cast<uint32_t*>(Hi + gr1 * outstride + col) = ph;
            *reinterpret_cast<uint32_t*>(Lo + gr1 * outstride + col) = pl;
        }
    }
}

// Merged q-proj (bid<256, routed) + kv-proj (bid>=256); fused norm/rope/split.
__global__ void __launch_bounds__(256, 2) gemm_qkv(
    const bf16* __restrict__ hh, const bf16* __restrict__ hl,
    const bf16* __restrict__ wqh, const bf16* __restrict__ wql,
    const bf16* __restrict__ wkvh, const bf16* __restrict__ wkvl,
    const int* __restrict__ sort_idx, const int* __restrict__ pos,
    const float* __restrict__ q_norm_w, const float* __restrict__ k_norm_w,
    bf16* __restrict__ qh, bf16* __restrict__ ql,
    bf16* __restrict__ kh2, bf16* __restrict__ kl2,
    bf16* __restrict__ vh, bf16* __restrict__ vl)
{
    extern __shared__ char smc[];
    float acc[2][8][4];
    int* rows = (int*)smc;
    int bid = blockIdx.x;
    const int wn = ((threadIdx.x >> 5) >> 2) * 64;

    if (bid < 256) {
        int x = bid & 15, y = (bid >> 4) & 3, z = bid >> 6;
        gemm_mainloop(hh, hl,
                      wqh + (size_t)z * HID * DQ, wql + (size_t)z * HID * DQ,
                      sort_idx, HID, y * 128, x * 128, z * CHUNK, smc, acc);
        epi_norm_rope(acc, rows, q_norm_w, pos, 0.125f, qh, ql, DQ, x * 128 + wn);
    } else {
        int bb = bid - 256;
        int x = bb & 7, y = bb >> 3;
        gemm_mainloop(hh, hl, wkvh, wkvl, nullptr,
                      HID, y * 128, x * 128, 0, smc, acc);
        if (x < 4) {
            epi_norm_rope(acc, rows, k_norm_w, pos, 1.0f, kh2, kl2, DKV, x * 128 + wn);
        } else {
            epi_split(acc, rows, vh, vl, DKV, (x - 4) * 128);
        }
    }
}

// o-proj (routed), fp32 output
__global__ void __launch_bounds__(256, 2) gemm_o(
    const bf16* __restrict__ oh, const bf16* __restrict__ ol,
    const bf16* __restrict__ woh, const bf16* __restrict__ wol,
    float* __restrict__ out, const int* __restrict__ sort_idx)
{
    extern __shared__ char smc[];
    float acc[2][8][4];
    int* rows = (int*)smc;
    int bid = blockIdx.x;
    int x = bid & 15, y = (bid >> 4) & 3, z = bid >> 6;
    gemm_mainloop(oh, ol,
                  woh + (size_t)z * DQ * HID, wol + (size_t)z * DQ * HID,
                  sort_idx, DQ, y * 128, x * 128, z * CHUNK, smc, acc);

    const int lane = threadIdx.x & 31;
    const int wid = threadIdx.x >> 5;
    const int wm = (wid & 3) * 32;
    const int wn = (wid >> 2) * 64;
    const int rq = lane >> 2;
    const int cq = (lane & 3) * 2;
#pragma unroll
    for (int mi = 0; mi < 2; mi++) {
        int r = wm + mi * 16 + rq;
        size_t gr0 = (size_t)rows[r];
        size_t gr1 = (size_t)rows[r + 8];
#pragma unroll
        for (int ni = 0; ni < 8; ni++) {
            int col = x * 128 + wn + ni * 8 + cq;
            *reinterpret_cast<float2*>(&out[gr0 * HID + col]) =
                make_float2(acc[mi][ni][0], acc[mi][ni][1]);
            *reinterpret_cast<float2*>(&out[gr1 * HID + col]) =
                make_float2(acc[mi][ni][2], acc[mi][ni][3]);
        }
    }
}

// ---------------------------------------------------------------------------
// Tensor-core flash attention, AQ=64 / 128 threads / 3 CTAs per SM.
// Q fragments loaded directly from gmem (no Q smem stage).
// ---------------------------------------------------------------------------
#define AQ 64
#define AK 64
#define LDK 72
#define KSM (AK * LDK)     // 4608
#define ASMEM (8 * KSM * 2 + 2 * AK * 4)   // 74240

__device__ __forceinline__ void attn_issue(
    uint32_t sbase, int s, int kt, int kvh, int tid,
    const bf16* __restrict__ kh_g, const bf16* __restrict__ kl_g,
    const bf16* __restrict__ vh_g, const bf16* __restrict__ vl_g,
    const int* __restrict__ pos, int* __restrict__ kpos_sm)
{
#pragma unroll
    for (int i = 0; i < 16; i++) {
        int f = tid + i * 128;
        int arr = f >> 9;
        int r = (f >> 3) & 63;
        int seg = f & 7;
        const bf16* src = (arr == 0) ? kh_g : (arr == 1) ? kl_g
                        : (arr == 2) ? vh_g : vl_g;
        uint32_t dst = sbase + (uint32_t)((s * 4 + arr) * KSM + r * LDK) * 2
                     + seg * 16;
        CP16(dst, src + (size_t)(kt * AK + r) * DKV + (size_t)kvh * HD + seg * 8);
    }
    if (tid < AK) kpos_sm[s * AK + tid] = pos[kt * AK + tid];
    CP_COMMIT();
}

__global__ void __launch_bounds__(128, 3) attn_mma(
    const bf16* __restrict__ qh_g, const bf16* __restrict__ ql_g,
    const bf16* __restrict__ kh_g, const bf16* __restrict__ kl_g,
    const bf16* __restrict__ vh_g, const bf16* __restrict__ vl_g,
    const int* __restrict__ pos,
    bf16* __restrict__ oh_g, bf16* __restrict__ ol_g)
{
    extern __shared__ char sm[];
    const uint32_t sbase = smem_u32(sm);
    int* kpos = (int*)(sm + (size_t)8 * KSM * 2);

    const int tid = threadIdx.x;
    const int w = tid >> 5;
    const int l = tid & 31;
    const int qt = gridDim.x - 1 - blockIdx.x;   // heavy tiles first
    const int h = blockIdx.y;
    const int kvh = h >> 2;
    const int q0 = qt * AQ;
    const int ntile = qt + 1;

    attn_issue(sbase, 0, 0, kvh, tid, kh_g, kl_g, vh_g, vl_g, pos, kpos);
    attn_issue(sbase, 1, 1 < ntile ? 1 : 0, kvh, tid, kh_g, kl_g, vh_g, vl_g, pos, kpos);

    const int rq = l >> 2;
    const int cq = l & 3;
    const int row0 = w * 16 + rq;

    // Q fragments straight from gmem
    uint32_t qfh[4][4], qfl[4][4];
    {
        const bf16* qbh = qh_g + (size_t)(q0 + row0) * DQ + h * HD;
        const bf16* qbl = ql_g + (size_t)(q0 + row0) * DQ + h * HD;
#pragma unroll
        for (int kf = 0; kf < 4; kf++) {
            int e0 = kf * 16 + cq * 2;
            qfh[kf][0] = *reinterpret_cast<const uint32_t*>(qbh + e0);
            qfh[kf][1] = *reinterpret_cast<const uint32_t*>(qbh + 8 * DQ + e0);
            qfh[kf][2] = *reinterpret_cast<const uint32_t*>(qbh + e0 + 8);
            qfh[kf][3] = *reinterpret_cast<const uint32_t*>(qbh + 8 * DQ + e0 + 8);
            qfl[kf][0] = *reinterpret_cast<const uint32_t*>(qbl + e0);
            qfl[kf][1] = *reinterpret_cast<const uint32_t*>(qbl + 8 * DQ + e0);
            qfl[kf][2] = *reinterpret_cast<const uint32_t*>(qbl + e0 + 8);
            qfl[kf][3] = *reinterpret_cast<const uint32_t*>(qbl + 8 * DQ + e0 + 8);
        }
    }
    const int qp0 = pos[q0 + row0];
    const int qp1 = pos[q0 + row0 + 8];

    float o[8][4];
#pragma unroll
    for (int nf = 0; nf < 8; nf++)
#pragma unroll
        for (int e = 0; e < 4; e++) o[nf][e] = 0.f;
    float m0 = -1e30f, m1 = -1e30f, l0 = 0.f, l1 = 0.f;

    const int lrow16 = l & 15;
    const int lsel = l >> 4;
    const uint32_t lnK = (((l >> 4) * 8 + (l & 7)) * LDK + ((l >> 3) & 1) * 8) * 2;

    for (int kt = 0; kt < ntile; kt++) {
        if (kt + 1 < ntile) asm volatile("cp.async.wait_group 1;" ::: "memory");
        else                asm volatile("cp.async.wait_group 0;" ::: "memory");
        __syncthreads();

        const int s = kt & 1;
        const uint32_t khb = sbase + (uint32_t)((s * 4 + 0) * KSM) * 2;
        const uint32_t vhb = sbase + (uint32_t)((s * 4 + 2) * KSM) * 2;
        const uint32_t vlb = sbase + (uint32_t)((s * 4 + 3) * KSM) * 2;

        float sv[8][4];
#pragma unroll
        for (int nf = 0; nf < 8; nf++)
#pragma unroll
            for (int e = 0; e < 4; e++) sv[nf][e] = 0.f;

#pragma unroll
        for (int kf = 0; kf < 4; kf++) {
#pragma unroll
            for (int np = 0; np < 4; np++) {
                uint32_t koff = khb + (uint32_t)(np * 16 * LDK) * 2 + kf * 32 + lnK;
                uint32_t b0, b1, b2, b3, c0, c1, c2, c3;
                LDSM_4(b0, b1, b2, b3, koff);
                LDSM_4(c0, c1, c2, c3, koff + KSM * 2);
                MMA16816(sv[2 * np], qfh[kf], b0, b1);
                MMA16816(sv[2 * np], qfh[kf], c0, c1);
                MMA16816(sv[2 * np], qfl[kf], b0, b1);
                MMA16816(sv[2 * np + 1], qfh[kf], b2, b3);
                MMA16816(sv[2 * np + 1], qfh[kf], c2, c3);
                MMA16816(sv[2 * np + 1], qfl[kf], b2, b3);
            }
        }

        if (kt == qt) {
            const int* kp = kpos + s * AK;
#pragma unroll
            for (int nf = 0; nf < 8; nf++) {
                int c = nf * 8 + cq * 2;
                int k0 = kp[c], k1 = kp[c + 1];
                if (k0 > qp0) sv[nf][0] = -1e30f;
                if (k1 > qp0) sv[nf][1] = -1e30f;
                if (k0 > qp1) sv[nf][2] = -1e30f;
                if (k1 > qp1) sv[nf][3] = -1e30f;
            }
        }

        float mt0 = -1e30f, mt1 = -1e30f;
#pragma unroll
        for (int nf = 0; nf < 8; nf++) {
            mt0 = fmaxf(mt0, fmaxf(sv[nf][0], sv[nf][1]));
            mt1 = fmaxf(mt1, fmaxf(sv[nf][2], sv[nf][3]));
        }
        mt0 = fmaxf(mt0, __shfl_xor_sync(0xffffffff, mt0, 1));
        mt0 = fmaxf(mt0, __shfl_xor_sync(0xffffffff, mt0, 2));
        mt1 = fmaxf(mt1, __shfl_xor_sync(0xffffffff, mt1, 1));
        mt1 = fmaxf(mt1, __shfl_xor_sync(0xffffffff, mt1, 2));
        float mn0 = fmaxf(m0, mt0), mn1 = fmaxf(m1, mt1);
        float a0 = __expf(m0 - mn0), a1 = __expf(m1 - mn1);
        m0 = mn0; m1 = mn1;
#pragma unroll
        for (int nf = 0; nf < 8; nf++) {
            o[nf][0] *= a0; o[nf][1] *= a0;
            o[nf][2] *= a1; o[nf][3] *= a1;
        }
        float rs0 = 0.f, rs1 = 0.f;
#pragma unroll
        for (int nf = 0; nf < 8; nf++) {
            sv[nf][0] = __expf(sv[nf][0] - mn0); rs0 += sv[nf][0];
            sv[nf][1] = __expf(sv[nf][1] - mn0); rs0 += sv[nf][1];
            sv[nf][2] = __expf(sv[nf][2] - mn1); rs1 += sv[nf][2];
            sv[nf][3] = __expf(sv[nf][3] - mn1); rs1 += sv[nf][3];
        }
        rs0 += __shfl_xor_sync(0xffffffff, rs0, 1);
        rs0 += __shfl_xor_sync(0xffffffff, rs0, 2);
        rs1 += __shfl_xor_sync(0xffffffff, rs1, 1);
        rs1 += __shfl_xor_sync(0xffffffff, rs1, 2);
        l0 = l0 * a0 + rs0;
        l1 = l1 * a1 + rs1;

#pragma unroll
        for (int kfk = 0; kfk < 4; kfk++) {
            uint32_t pah[4], pal[4];
            splitpack2(sv[2 * kfk][0], sv[2 * kfk][1], pah[0], pal[0]);
            splitpack2(sv[2 * kfk][2], sv[2 * kfk][3], pah[1], pal[1]);
            splitpack2(sv[2 * kfk + 1][0], sv[2 * kfk + 1][1], pah[2], pal[2]);
            splitpack2(sv[2 * kfk + 1][2], sv[2 * kfk + 1][3], pah[3], pal[3]);

            uint32_t vfh[8][2], vfl[8][2];
#pragma unroll
            for (int nfp = 0; nfp < 4; nfp++) {
                uint32_t off = (uint32_t)((kfk * 16 + lrow16) * LDK
                                          + nfp * 16 + lsel * 8) * 2;
                uint32_t r0, r1, r2, r3;
                LDSM_T4(r0, r1, r2, r3, vhb + off);
                vfh[2 * nfp][0] = r0;     vfh[2 * nfp][1] = r1;
                vfh[2 * nfp + 1][0] = r2; vfh[2 * nfp + 1][1] = r3;
                LDSM_T4(r0, r1, r2, r3, vlb + off);
                vfl[2 * nfp][0] = r0;     vfl[2 * nfp][1] = r1;
                vfl[2 * nfp + 1][0] = r2; vfl[2 * nfp + 1][1] = r3;
            }
#pragma unroll
            for (int nf = 0; nf < 8; nf++) {
                MMA16816(o[nf], pah, vfh[nf][0], vfh[nf][1]);
                MMA16816(o[nf], pah, vfl[nf][0], vfl[nf][1]);
                MMA16816(o[nf], pal, vfh[nf][0], vfh[nf][1]);
            }
        }

        __syncthreads();
        if (kt + 2 < ntile)
            attn_issue(sbase, s, kt + 2, kvh, tid, kh_g, kl_g, vh_g, vl_g, pos, kpos);
    }

    float i0 = 1.f / l0, i1 = 1.f / l1;
    int g0 = q0 + w * 16 + rq;
    int g1 = g0 + 8;
#pragma unroll
    for (int nf = 0; nf < 8; nf++) {
        int col = h * HD + nf * 8 + cq * 2;
        uint32_t ph, pl;
        splitpack2(o[nf][0] * i0, o[nf][1] * i0, ph, pl);
        *reinterpret_cast<uint32_t*>(oh_g + (size_t)g0 * DQ + col) = ph;
        *reinterpret_cast<uint32_t*>(ol_g + (size_t)g0 * DQ + col) = pl;
        splitpack2(o[nf][2] * i1, o[nf][3] * i1, ph, pl);
        *reinterpret_cast<uint32_t*>(oh_g + (size_t)g1 * DQ + col) = ph;
        *reinterpret_cast<uint32_t*>(ol_g + (size_t)g1 * DQ + col) = pl;
    }
}

// ---------------------------------------------------------------------------
extern "C" void kernel_launch(void* const* d_in, const int* in_sizes, int n_in,
                              void* d_out, int out_size)
{
    const float* hidden    = (const float*)d_in[0];
    const int*   positions = (const int*)  d_in[1];
    const int*   sort_idx  = (const int*)  d_in[2];
    const float* q_proj_w  = (const float*)d_in[3];
    const float* o_proj_w  = (const float*)d_in[4];
    const float* k_w       = (const float*)d_in[5];
    const float* v_w       = (const float*)d_in[6];
    const float* q_norm_w  = (const float*)d_in[7];
    const float* k_norm_w  = (const float*)d_in[8];
    float* out = (float*)d_out;

    bf16 *hh, *hl, *oh, *ol, *qh, *ql, *kh2, *kl2, *vh, *vl;
    bf16 *wqh, *wql, *woh, *wol, *wkvh, *wkvl;
    cudaGetSymbolAddress((void**)&hh, g_hh);
    cudaGetSymbolAddress((void**)&hl, g_hl);
    cudaGetSymbolAddress((void**)&oh, g_oh);
    cudaGetSymbolAddress((void**)&ol, g_ol);
    cudaGetSymbolAddress((void**)&qh, g_qh);
    cudaGetSymbolAddress((void**)&ql, g_ql);
    cudaGetSymbolAddress((void**)&kh2, g_kh2);
    cudaGetSymbolAddress((void**)&kl2, g_kl2);
    cudaGetSymbolAddress((void**)&vh, g_vh);
    cudaGetSymbolAddress((void**)&vl, g_vl);
    cudaGetSymbolAddress((void**)&wqh, g_wq_h);
    cudaGetSymbolAddress((void**)&wql, g_wq_l);
    cudaGetSymbolAddress((void**)&woh, g_wo_h);
    cudaGetSymbolAddress((void**)&wol, g_wo_l);
    cudaGetSymbolAddress((void**)&wkvh, g_wkv_h);
    cudaGetSymbolAddress((void**)&wkvl, g_wkv_l);

    cudaFuncSetAttribute(gemm_qkv, cudaFuncAttributeMaxDynamicSharedMemorySize, GEMM_SMEM);
    cudaFuncSetAttribute(gemm_o, cudaFuncAttributeMaxDynamicSharedMemorySize, GEMM_SMEM);
    cudaFuncSetAttribute(attn_mma, cudaFuncAttributeMaxDynamicSharedMemorySize, ASMEM);

    // 1) all weight transposes + hidden split
    prep_inputs<<<34816 + 4096, 256>>>(
        q_proj_w, o_proj_w, k_w, v_w, hidden,
        wqh, wql, woh, wol, wkvh, wkvl, hh, hl);

    // 2) q-proj + kv-proj with fused RMSNorm/RoPE/split epilogues
    gemm_qkv<<<384, 256, GEMM_SMEM>>>(
        hh, hl, wqh, wql, wkvh, wkvl, sort_idx, positions,
        q_norm_w, k_norm_w, qh, ql, kh2, kl2, vh, vl);

    // 3) flash attention (3 CTAs/SM)
    attn_mma<<<dim3(NTOK / AQ, NH), 128, ASMEM>>>(
        qh, ql, kh2, kl2, vh, vl, positions, oh, ol);

    // 4) o-proj (routed)
    gemm_o<<<256, 256, GEMM_SMEM>>>(oh, ol, woh, wol, out, sort_idx);
}

// round 8
// speedup vs baseline: 1.0525x; 1.0525x over previous
#include <cuda_runtime.h>
#include <cuda_bf16.h>
#include <cstdint>
#include <math.h>

// Problem constants
#define NTOK 2048
#define HID 2048
#define NH 32
#define NKV 8
#define HD 64
#define NE 4
#define CHUNK (NTOK / NE)   // 512
#define DQ (NH * HD)        // 2048
#define DKV (NKV * HD)      // 512

typedef __nv_bfloat16 bf16;

// Scratch
__device__ bf16 g_hh[(size_t)NTOK * HID];
__device__ bf16 g_hl[(size_t)NTOK * HID];
__device__ bf16 g_oh[(size_t)NTOK * DQ];
__device__ bf16 g_ol[(size_t)NTOK * DQ];

__device__ bf16 g_qh[(size_t)NTOK * DQ];
__device__ bf16 g_ql[(size_t)NTOK * DQ];
__device__ bf16 g_kh2[(size_t)NTOK * DKV];
__device__ bf16 g_kl2[(size_t)NTOK * DKV];
__device__ bf16 g_vh[(size_t)NTOK * DKV];
__device__ bf16 g_vl[(size_t)NTOK * DKV];

// Weight splits in ORIGINAL [K][N] layout (no transpose)
__device__ bf16 g_wq_h[(size_t)NE * HID * DQ];
__device__ bf16 g_wq_l[(size_t)NE * HID * DQ];
__device__ bf16 g_wo_h[(size_t)NE * DQ * HID];
__device__ bf16 g_wo_l[(size_t)NE * DQ * HID];
__device__ bf16 g_wk_h[(size_t)HID * DKV];
__device__ bf16 g_wk_l[(size_t)HID * DKV];
__device__ bf16 g_wv_h[(size_t)HID * DKV];
__device__ bf16 g_wv_l[(size_t)HID * DKV];

__device__ float2 g_rope[(size_t)NTOK * 32];   // (cos, sin) per (token, freq)

// ---------------------------------------------------------------------------
__device__ __forceinline__ uint32_t smem_u32(const void* p) {
    uint32_t a;
    asm("{ .reg .u64 t; cvta.to.shared.u64 t, %1; cvt.u32.u64 %0, t; }"
        : "=r"(a) : "l"(p));
    return a;
}

#define CP16(dst, src) \
    asm volatile("cp.async.cg.shared.global [%0], [%1], 16;" \
        :: "r"(dst), "l"(src) : "memory")
#define CP_COMMIT() asm volatile("cp.async.commit_group;" ::: "memory")

#define MMA16816(d, a, b0, b1) \
    asm volatile("mma.sync.aligned.m16n8k16.row.col.f32.bf16.bf16.f32 " \
        "{%0,%1,%2,%3}, {%4,%5,%6,%7}, {%8,%9}, {%0,%1,%2,%3};" \
        : "+f"((d)[0]), "+f"((d)[1]), "+f"((d)[2]), "+f"((d)[3]) \
        : "r"((a)[0]), "r"((a)[1]), "r"((a)[2]), "r"((a)[3]), "r"(b0), "r"(b1))

#define LDSM_4(r0, r1, r2, r3, a) \
    asm volatile("ldmatrix.sync.aligned.m8n8.x4.shared.b16 {%0,%1,%2,%3}, [%4];" \
        : "=r"(r0), "=r"(r1), "=r"(r2), "=r"(r3) : "r"(a))

#define LDSM_T4(r0, r1, r2, r3, a) \
    asm volatile("ldmatrix.sync.aligned.m8n8.x4.trans.shared.b16 {%0,%1,%2,%3}, [%4];" \
        : "=r"(r0), "=r"(r1), "=r"(r2), "=r"(r3) : "r"(a))

__device__ __forceinline__ void bf_split(float f, bf16& h, bf16& l) {
    h = __float2bfloat16(f);
    l = __float2bfloat16(f - __bfloat162float(h));
}

__device__ __forceinline__ void splitpack2(float a, float b, uint32_t& hi, uint32_t& lo) {
    bf16 ha, la, hb, lb;
    bf_split(a, ha, la);
    bf_split(b, hb, lb);
    hi = ((uint32_t)__bfloat16_as_ushort(hb) << 16) | __bfloat16_as_ushort(ha);
    lo = ((uint32_t)__bfloat16_as_ushort(lb) << 16) | __bfloat16_as_ushort(la);
}

// ---------------------------------------------------------------------------
// Prep: coalesced fp32->bf16 hi/lo splits (no transposes) + RoPE table.
// ---------------------------------------------------------------------------
__device__ __forceinline__ void split4(const float* __restrict__ X,
                                       bf16* __restrict__ Hi, bf16* __restrict__ Lo,
                                       int i) {
    float4 v = reinterpret_cast<const float4*>(X)[i];
    bf16 h[4], l[4];
    bf_split(v.x, h[0], l[0]); bf_split(v.y, h[1], l[1]);
    bf_split(v.z, h[2], l[2]); bf_split(v.w, h[3], l[3]);
    reinterpret_cast<uint2*>(Hi)[i] = *reinterpret_cast<uint2*>(h);
    reinterpret_cast<uint2*>(Lo)[i] = *reinterpret_cast<uint2*>(l);
}

// block ranges (in 256-thread blocks of float4 work)
#define PB_Q 16384
#define PB_O 16384
#define PB_K 1024
#define PB_V 1024
#define PB_H 4096
#define PB_R 256
#define PREP_BLOCKS (PB_Q + PB_O + PB_K + PB_V + PB_H + PB_R)

__global__ void __launch_bounds__(256) prep_split(
    const float* __restrict__ q_proj_w, const float* __restrict__ o_proj_w,
    const float* __restrict__ k_w, const float* __restrict__ v_w,
    const float* __restrict__ hidden, const int* __restrict__ pos,
    bf16* __restrict__ wqh, bf16* __restrict__ wql,
    bf16* __restrict__ woh, bf16* __restrict__ wol,
    bf16* __restrict__ wkh, bf16* __restrict__ wkl,
    bf16* __restrict__ wvh, bf16* __restrict__ wvl,
    bf16* __restrict__ hh, bf16* __restrict__ hl,
    float2* __restrict__ rope)
{
    int b = blockIdx.x;
    int tid = threadIdx.x;
    if (b < PB_Q) {
        split4(q_proj_w, wqh, wql, b * 256 + tid);
    } else if (b < PB_Q + PB_O) {
        split4(o_proj_w, woh, wol, (b - PB_Q) * 256 + tid);
    } else if (b < PB_Q + PB_O + PB_K) {
        split4(k_w, wkh, wkl, (b - PB_Q - PB_O) * 256 + tid);
    } else if (b < PB_Q + PB_O + PB_K + PB_V) {
        split4(v_w, wvh, wvl, (b - PB_Q - PB_O - PB_K) * 256 + tid);
    } else if (b < PB_Q + PB_O + PB_K + PB_V + PB_H) {
        split4(hidden, hh, hl, (b - PB_Q - PB_O - PB_K - PB_V) * 256 + tid);
    } else {
        int i = (b - PB_Q - PB_O - PB_K - PB_V - PB_H) * 256 + tid;  // 0..65535
        int t = i >> 5;
        int c = i & 31;
        float inv = powf(10000.0f, -(float)c * (1.0f / 32.0f));
        float s, cs;
        sincosf((float)pos[t] * inv, &s, &cs);
        rope[i] = make_float2(cs, s);
    }
}

// ---------------------------------------------------------------------------
// bf16x3 mma.sync GEMM mainloop (128x128 tile), B from [K][N] via ldmatrix.trans.
// ---------------------------------------------------------------------------
#define LDA 40
#define LDB 136
#define A_E (128 * LDA)           // 5120 elements per A operand
#define B_E (32 * LDB)            // 4352 elements per B operand
#define STAGE_EL (2 * A_E + 2 * B_E)   // 18944
#define GEMM_SMEM (1024 + 2 * STAGE_EL * 2)   // 76800

__device__ __forceinline__ void issue_tile(
    uint32_t sB, int s, int kb,
    const bf16* __restrict__ Agh, const bf16* __restrict__ Agl,
    const bf16* __restrict__ Bgh, const bf16* __restrict__ Bgl,
    const int* __restrict__ rows, int n0, int K, int Nd, int tid)
{
#pragma unroll
    for (int rep = 0; rep < 2; rep++) {
        int f = tid + rep * 256;               // 0..511
        // A: [M=128][BK=32], row m, float4-chunk q
        int m = f >> 2;
        int q = f & 3;
        uint32_t adst = sB + (uint32_t)s * (STAGE_EL * 2) + m * (LDA * 2) + q * 16;
        size_t asrc = (size_t)rows[m] * K + kb + q * 8;
        CP16(adst,           Agh + asrc);
        CP16(adst + A_E * 2, Agl + asrc);
        // B: [BK=32][N=128] from [K][N] source, row kk, 16B seg
        int kk = f >> 4;
        int seg = f & 15;
        uint32_t bdst = sB + (uint32_t)s * (STAGE_EL * 2) + (2 * A_E + kk * LDB) * 2
                      + seg * 16;
        size_t bsrc = (size_t)(kb + kk) * Nd + n0 + seg * 8;
        CP16(bdst,           Bgh + bsrc);
        CP16(bdst + B_E * 2, Bgl + bsrc);
    }
}

__device__ __forceinline__ void gemm_mainloop(
    const bf16* __restrict__ Agh, const bf16* __restrict__ Agl,
    const bf16* __restrict__ Bh_g, const bf16* __restrict__ Bl_g,
    const int* __restrict__ idx,
    int K, int Nd, int m0, int n0, int zchunk, char* smc,
    float acc[2][8][4])
{
    int* rows = (int*)smc;
    const uint32_t sB = smem_u32(smc + 1024);
    const int tid = threadIdx.x;
    const int wid = tid >> 5;
    const int lane = tid & 31;

    if (tid < 128) {
        int lr = zchunk + m0 + tid;
        rows[tid] = idx ? idx[lr] : lr;
    }
    __syncthreads();

    const int wm = (wid & 3) * 32;
    const int wn = (wid >> 2) * 64;
    const uint32_t lnA = ((((lane >> 3) & 1) * 8 + (lane & 7)) * LDA + (lane >> 4) * 8) * 2;
    const uint32_t lnBT = ((lane & 15) * LDB + (lane >> 4) * 8) * 2;

#pragma unroll
    for (int a = 0; a < 2; a++)
#pragma unroll
        for (int b = 0; b < 8; b++)
#pragma unroll
            for (int c = 0; c < 4; c++) acc[a][b][c] = 0.f;

    const int nkt = K / 32;
    issue_tile(sB, 0, 0, Agh, Agl, Bh_g, Bl_g, rows, n0, K, Nd, tid); CP_COMMIT();
    issue_tile(sB, 1, 32, Agh, Agl, Bh_g, Bl_g, rows, n0, K, Nd, tid); CP_COMMIT();

    for (int kt = 0; kt < nkt; kt++) {
        if (kt + 1 < nkt) asm volatile("cp.async.wait_group 1;" ::: "memory");
        else              asm volatile("cp.async.wait_group 0;" ::: "memory");
        __syncthreads();

        const int s = kt & 1;
        const uint32_t sb_s = sB + (uint32_t)s * (STAGE_EL * 2);
        const uint32_t bb_s = sb_s + (uint32_t)(2 * A_E) * 2;

#pragma unroll
        for (int ks = 0; ks < 32; ks += 16) {
            uint32_t ah[2][4], al[2][4];
            uint32_t abase = sb_s + (uint32_t)(wm * LDA + ks) * 2 + lnA;
#pragma unroll
            for (int mi = 0; mi < 2; mi++) {
                LDSM_4(ah[mi][0], ah[mi][1], ah[mi][2], ah[mi][3],
                       abase + mi * (16 * LDA * 2));
                LDSM_4(al[mi][0], al[mi][1], al[mi][2], al[mi][3],
                       abase + mi * (16 * LDA * 2) + A_E * 2);
            }
#pragma unroll
            for (int np = 0; np < 4; np++) {
                uint32_t boff = bb_s + (uint32_t)(ks * LDB + wn + np * 16) * 2 + lnBT;
                uint32_t bh0, bh1, bh2, bh3, bl0, bl1, bl2, bl3;
                LDSM_T4(bh0, bh1, bh2, bh3, boff);
                LDSM_T4(bl0, bl1, bl2, bl3, boff + B_E * 2);
#pragma unroll
                for (int mi = 0; mi < 2; mi++) {
                    MMA16816(acc[mi][2 * np], ah[mi], bh0, bh1);
                    MMA16816(acc[mi][2 * np], ah[mi], bl0, bl1);
                    MMA16816(acc[mi][2 * np], al[mi], bh0, bh1);
                    MMA16816(acc[mi][2 * np + 1], ah[mi], bh2, bh3);
                    MMA16816(acc[mi][2 * np + 1], ah[mi], bl2, bl3);
                    MMA16816(acc[mi][2 * np + 1], al[mi], bh2, bh3);
                }
            }
        }
        __syncthreads();
        if (kt + 2 < nkt) {
            issue_tile(sB, s, (kt + 2) * 32, Agh, Agl, Bh_g, Bl_g, rows, n0, K, Nd, tid);
            CP_COMMIT();
        }
    }
}

// Epilogue: fused RMSNorm + NeoX RoPE (table) + bf16 split (warp tile = one head)
__device__ __forceinline__ void epi_norm_rope(
    float acc[2][8][4], const int* __restrict__ rows,
    const float* __restrict__ w, const float2* __restrict__ rope, float sc,
    bf16* __restrict__ Hi, bf16* __restrict__ Lo, int outstride, int headcol0)
{
    const int lane = threadIdx.x & 31;
    const int wid = threadIdx.x >> 5;
    const int wm = (wid & 3) * 32;
    const int rq = lane >> 2, cq = lane & 3;

#pragma unroll
    for (int mi = 0; mi < 2; mi++) {
#pragma unroll
        for (int hf = 0; hf < 2; hf++) {
            int r = wm + mi * 16 + rq + hf * 8;
            int gr = rows[r];
            float ss = 0.f;
#pragma unroll
            for (int nf = 0; nf < 8; nf++) {
                float a = acc[mi][nf][hf * 2], b = acc[mi][nf][hf * 2 + 1];
                ss += a * a + b * b;
            }
            ss += __shfl_xor_sync(0xffffffff, ss, 1);
            ss += __shfl_xor_sync(0xffffffff, ss, 2);
            float rn = rsqrtf(ss * (1.0f / 64.0f) + 1e-6f) * sc;
            const float2* rt = rope + (size_t)gr * 32;
#pragma unroll
            for (int nf = 0; nf < 4; nf++) {
                float o1[2], o2[2];
#pragma unroll
                for (int par = 0; par < 2; par++) {
                    int c = nf * 8 + cq * 2 + par;
                    float y1 = acc[mi][nf][hf * 2 + par] * rn * w[c];
                    float y2 = acc[mi][nf + 4][hf * 2 + par] * rn * w[c + 32];
                    float2 cs = rt[c];
                    o1[par] = y1 * cs.x - y2 * cs.y;
                    o2[par] = y2 * cs.x + y1 * cs.y;
                }
                uint32_t ph, pl;
                size_t base = (size_t)gr * outstride + headcol0 + nf * 8 + cq * 2;
                splitpack2(o1[0], o1[1], ph, pl);
                *reinterpret_cast<uint32_t*>(Hi + base) = ph;
                *reinterpret_cast<uint32_t*>(Lo + base) = pl;
                splitpack2(o2[0], o2[1], ph, pl);
                *reinterpret_cast<uint32_t*>(Hi + base + 32) = ph;
                *reinterpret_cast<uint32_t*>(Lo + base + 32) = pl;
            }
        }
    }
}

// Epilogue: plain bf16 split (v)
__device__ __forceinline__ void epi_split(
    float acc[2][8][4], const int* __restrict__ rows,
    bf16* __restrict__ Hi, bf16* __restrict__ Lo, int outstride, int col0)
{
    const int lane = threadIdx.x & 31;
    const int wid = threadIdx.x >> 5;
    const int wm = (wid & 3) * 32;
    const int wn = (wid >> 2) * 64;
    const int rq = lane >> 2, cq = lane & 3;
#pragma unroll
    for (int mi = 0; mi < 2; mi++) {
        int r = wm + mi * 16 + rq;
        size_t gr0 = (size_t)rows[r];
        size_t gr1 = (size_t)rows[r + 8];
#pragma unroll
        for (int nf = 0; nf < 8; nf++) {
            int col = col0 + wn + nf * 8 + cq * 2;
            uint32_t ph, pl;
            splitpack2(acc[mi][nf][0], acc[mi][nf][1], ph, pl);
            *reinterpret_cast<uint32_t*>(Hi + gr0 * outstride + col) = ph;
            *reinterpret_cast<uint32_t*>(Lo + gr0 * outstride + col) = pl;
            splitpack2(acc[mi][nf][2], acc[mi][nf][3], ph, pl);
            *reinterpret_cast<uint32_t*>(Hi + gr1 * outstride + col) = ph;
            *reinterpret_cast<uint32_t*>(Lo + gr1 * outstride + col) = pl;
        }
    }
}

// Merged q-proj (bid<256, routed) + k-proj + v-proj; fused norm/rope/split.
__global__ void __launch_bounds__(256, 2) gemm_qkv(
    const bf16* __restrict__ hh, const bf16* __restrict__ hl,
    const bf16* __restrict__ wqh, const bf16* __restrict__ wql,
    const bf16* __restrict__ wkh, const bf16* __restrict__ wkl,
    const bf16* __restrict__ wvh, const bf16* __restrict__ wvl,
    const int* __restrict__ sort_idx, const float2* __restrict__ rope,
    const float* __restrict__ q_norm_w, const float* __restrict__ k_norm_w,
    bf16* __restrict__ qh, bf16* __restrict__ ql,
    bf16* __restrict__ kh2, bf16* __restrict__ kl2,
    bf16* __restrict__ vh, bf16* __restrict__ vl)
{
    extern __shared__ char smc[];
    float acc[2][8][4];
    int* rows = (int*)smc;
    int bid = blockIdx.x;
    const int wn = ((threadIdx.x >> 5) >> 2) * 64;

    if (bid < 256) {
        int x = bid & 15, y = (bid >> 4) & 3, z = bid >> 6;
        gemm_mainloop(hh, hl,
                      wqh + (size_t)z * HID * DQ, wql + (size_t)z * HID * DQ,
                      sort_idx, HID, DQ, y * 128, x * 128, z * CHUNK, smc, acc);
        epi_norm_rope(acc, rows, q_norm_w, rope, 0.125f, qh, ql, DQ, x * 128 + wn);
    } else {
        int bb = bid - 256;
        int x = bb & 7, y = bb >> 3;
        if (x < 4) {
            gemm_mainloop(hh, hl, wkh, wkl, nullptr,
                          HID, DKV, y * 128, x * 128, 0, smc, acc);
            epi_norm_rope(acc, rows, k_norm_w, rope, 1.0f, kh2, kl2, DKV, x * 128 + wn);
        } else {
            gemm_mainloop(hh, hl, wvh, wvl, nullptr,
                          HID, DKV, y * 128, (x - 4) * 128, 0, smc, acc);
            epi_split(acc, rows, vh, vl, DKV, (x - 4) * 128);
        }
    }
}

// o-proj (routed), fp32 output
__global__ void __launch_bounds__(256, 2) gemm_o(
    const bf16* __restrict__ oh, const bf16* __restrict__ ol,
    const bf16* __restrict__ woh, const bf16* __restrict__ wol,
    float* __restrict__ out, const int* __restrict__ sort_idx)
{
    extern __shared__ char smc[];
    float acc[2][8][4];
    int* rows = (int*)smc;
    int bid = blockIdx.x;
    int x = bid & 15, y = (bid >> 4) & 3, z = bid >> 6;
    gemm_mainloop(oh, ol,
                  woh + (size_t)z * DQ * HID, wol + (size_t)z * DQ * HID,
                  sort_idx, DQ, HID, y * 128, x * 128, z * CHUNK, smc, acc);

    const int lane = threadIdx.x & 31;
    const int wid = threadIdx.x >> 5;
    const int wm = (wid & 3) * 32;
    const int wn = (wid >> 2) * 64;
    const int rq = lane >> 2;
    const int cq = (lane & 3) * 2;
#pragma unroll
    for (int mi = 0; mi < 2; mi++) {
        int r = wm + mi * 16 + rq;
        size_t gr0 = (size_t)rows[r];
        size_t gr1 = (size_t)rows[r + 8];
#pragma unroll
        for (int ni = 0; ni < 8; ni++) {
            int col = x * 128 + wn + ni * 8 + cq;
            *reinterpret_cast<float2*>(&out[gr0 * HID + col]) =
                make_float2(acc[mi][ni][0], acc[mi][ni][1]);
            *reinterpret_cast<float2*>(&out[gr1 * HID + col]) =
                make_float2(acc[mi][ni][2], acc[mi][ni][3]);
        }
    }
}

// ---------------------------------------------------------------------------
// Tensor-core flash attention, AQ=64 / 128 threads / 3 CTAs per SM.
// ---------------------------------------------------------------------------
#define AQ 64
#define AK 64
#define LDK 72
#define KSM (AK * LDK)     // 4608
#define ASMEM (8 * KSM * 2 + 2 * AK * 4)   // 74240

__device__ __forceinline__ void attn_issue(
    uint32_t sbase, int s, int kt, int kvh, int tid,
    const bf16* __restrict__ kh_g, const bf16* __restrict__ kl_g,
    const bf16* __restrict__ vh_g, const bf16* __restrict__ vl_g,
    const int* __restrict__ pos, int* __restrict__ kpos_sm)
{
#pragma unroll
    for (int i = 0; i < 16; i++) {
        int f = tid + i * 128;
        int arr = f >> 9;
        int r = (f >> 3) & 63;
        int seg = f & 7;
        const bf16* src = (arr == 0) ? kh_g : (arr == 1) ? kl_g
                        : (arr == 2) ? vh_g : vl_g;
        uint32_t dst = sbase + (uint32_t)((s * 4 + arr) * KSM + r * LDK) * 2
                     + seg * 16;
        CP16(dst, src + (size_t)(kt * AK + r) * DKV + (size_t)kvh * HD + seg * 8);
    }
    if (tid < AK) kpos_sm[s * AK + tid] = pos[kt * AK + tid];
    CP_COMMIT();
}

__global__ void __launch_bounds__(128, 3) attn_mma(
    const bf16* __restrict__ qh_g, const bf16* __restrict__ ql_g,
    const bf16* __restrict__ kh_g, const bf16* __restrict__ kl_g,
    const bf16* __restrict__ vh_g, const bf16* __restrict__ vl_g,
    const int* __restrict__ pos,
    bf16* __restrict__ oh_g, bf16* __restrict__ ol_g)
{
    extern __shared__ char sm[];
    const uint32_t sbase = smem_u32(sm);
    int* kpos = (int*)(sm + (size_t)8 * KSM * 2);

    const int tid = threadIdx.x;
    const int w = tid >> 5;
    const int l = tid & 31;
    const int qt = gridDim.x - 1 - blockIdx.x;
    const int h = blockIdx.y;
    const int kvh = h >> 2;
    const int q0 = qt * AQ;
    const int ntile = qt + 1;

    attn_issue(sbase, 0, 0, kvh, tid, kh_g, kl_g, vh_g, vl_g, pos, kpos);
    attn_issue(sbase, 1, 1 < ntile ? 1 : 0, kvh, tid, kh_g, kl_g, vh_g, vl_g, pos, kpos);

    const int rq = l >> 2;
    const int cq = l & 3;
    const int row0 = w * 16 + rq;

    uint32_t qfh[4][4], qfl[4][4];
    {
        const bf16* qbh = qh_g + (size_t)(q0 + row0) * DQ + h * HD;
        const bf16* qbl = ql_g + (size_t)(q0 + row0) * DQ + h * HD;
#pragma unroll
        for (int kf = 0; kf < 4; kf++) {
            int e0 = kf * 16 + cq * 2;
            qfh[kf][0] = *reinterpret_cast<const uint32_t*>(qbh + e0);
            qfh[kf][1] = *reinterpret_cast<const uint32_t*>(qbh + 8 * DQ + e0);
            qfh[kf][2] = *reinterpret_cast<const uint32_t*>(qbh + e0 + 8);
            qfh[kf][3] = *reinterpret_cast<const uint32_t*>(qbh + 8 * DQ + e0 + 8);
            qfl[kf][0] = *reinterpret_cast<const uint32_t*>(qbl + e0);
            qfl[kf][1] = *reinterpret_cast<const uint32_t*>(qbl + 8 * DQ + e0);
            qfl[kf][2] = *reinterpret_cast<const uint32_t*>(qbl + e0 + 8);
            qfl[kf][3] = *reinterpret_cast<const uint32_t*>(qbl + 8 * DQ + e0 + 8);
        }
    }
    const int qp0 = pos[q0 + row0];
    const int qp1 = pos[q0 + row0 + 8];

    float o[8][4];
#pragma unroll
    for (int nf = 0; nf < 8; nf++)
#pragma unroll
        for (int e = 0; e < 4; e++) o[nf][e] = 0.f;
    float m0 = -1e30f, m1 = -1e30f, l0 = 0.f, l1 = 0.f;

    const int lrow16 = l & 15;
    const int lsel = l >> 4;
    const uint32_t lnK = (((l >> 4) * 8 + (l & 7)) * LDK + ((l >> 3) & 1) * 8) * 2;

    for (int kt = 0; kt < ntile; kt++) {
        if (kt + 1 < ntile) asm volatile("cp.async.wait_group 1;" ::: "memory");
        else                asm volatile("cp.async.wait_group 0;" ::: "memory");
        __syncthreads();

        const int s = kt & 1;
        const uint32_t khb = sbase + (uint32_t)((s * 4 + 0) * KSM) * 2;
        const uint32_t vhb = sbase + (uint32_t)((s * 4 + 2) * KSM) * 2;
        const uint32_t vlb = sbase + (uint32_t)((s * 4 + 3) * KSM) * 2;

        float sv[8][4];
#pragma unroll
        for (int nf = 0; nf < 8; nf++)
#pragma unroll
            for (int e = 0; e < 4; e++) sv[nf][e] = 0.f;

#pragma unroll
        for (int kf = 0; kf < 4; kf++) {
#pragma unroll
            for (int np = 0; np < 4; np++) {
                uint32_t koff = khb + (uint32_t)(np * 16 * LDK) * 2 + kf * 32 + lnK;
                uint32_t b0, b1, b2, b3, c0, c1, c2, c3;
                LDSM_4(b0, b1, b2, b3, koff);
                LDSM_4(c0, c1, c2, c3, koff + KSM * 2);
                MMA16816(sv[2 * np], qfh[kf], b0, b1);
                MMA16816(sv[2 * np], qfh[kf], c0, c1);
                MMA16816(sv[2 * np], qfl[kf], b0, b1);
                MMA16816(sv[2 * np + 1], qfh[kf], b2, b3);
                MMA16816(sv[2 * np + 1], qfh[kf], c2, c3);
                MMA16816(sv[2 * np + 1], qfl[kf], b2, b3);
            }
        }

        if (kt == qt) {
            const int* kp = kpos + s * AK;
#pragma unroll
            for (int nf = 0; nf < 8; nf++) {
                int c = nf * 8 + cq * 2;
                int k0 = kp[c], k1 = kp[c + 1];
                if (k0 > qp0) sv[nf][0] = -1e30f;
                if (k1 > qp0) sv[nf][1] = -1e30f;
                if (k0 > qp1) sv[nf][2] = -1e30f;
                if (k1 > qp1) sv[nf][3] = -1e30f;
            }
        }

        float mt0 = -1e30f, mt1 = -1e30f;
#pragma unroll
        for (int nf = 0; nf < 8; nf++) {
            mt0 = fmaxf(mt0, fmaxf(sv[nf][0], sv[nf][1]));
            mt1 = fmaxf(mt1, fmaxf(sv[nf][2], sv[nf][3]));
        }
        mt0 = fmaxf(mt0, __shfl_xor_sync(0xffffffff, mt0, 1));
        mt0 = fmaxf(mt0, __shfl_xor_sync(0xffffffff, mt0, 2));
        mt1 = fmaxf(mt1, __shfl_xor_sync(0xffffffff, mt1, 1));
        mt1 = fmaxf(mt1, __shfl_xor_sync(0xffffffff, mt1, 2));
        float mn0 = fmaxf(m0, mt0), mn1 = fmaxf(m1, mt1);
        float a0 = __expf(m0 - mn0), a1 = __expf(m1 - mn1);
        m0 = mn0; m1 = mn1;
#pragma unroll
        for (int nf = 0; nf < 8; nf++) {
            o[nf][0] *= a0; o[nf][1] *= a0;
            o[nf][2] *= a1; o[nf][3] *= a1;
        }
        float rs0 = 0.f, rs1 = 0.f;
#pragma unroll
        for (int nf = 0; nf < 8; nf++) {
            sv[nf][0] = __expf(sv[nf][0] - mn0); rs0 += sv[nf][0];
            sv[nf][1] = __expf(sv[nf][1] - mn0); rs0 += sv[nf][1];
            sv[nf][2] = __expf(sv[nf][2] - mn1); rs1 += sv[nf][2];
            sv[nf][3] = __expf(sv[nf][3] - mn1); rs1 += sv[nf][3];
        }
        rs0 += __shfl_xor_sync(0xffffffff, rs0, 1);
        rs0 += __shfl_xor_sync(0xffffffff, rs0, 2);
        rs1 += __shfl_xor_sync(0xffffffff, rs1, 1);
        rs1 += __shfl_xor_sync(0xffffffff, rs1, 2);
        l0 = l0 * a0 + rs0;
        l1 = l1 * a1 + rs1;

#pragma unroll
        for (int kfk = 0; kfk < 4; kfk++) {
            uint32_t pah[4], pal[4];
            splitpack2(sv[2 * kfk][0], sv[2 * kfk][1], pah[0], pal[0]);
            splitpack2(sv[2 * kfk][2], sv[2 * kfk][3], pah[1], pal[1]);
            splitpack2(sv[2 * kfk + 1][0], sv[2 * kfk + 1][1], pah[2], pal[2]);
            splitpack2(sv[2 * kfk + 1][2], sv[2 * kfk + 1][3], pah[3], pal[3]);

            uint32_t vfh[8][2], vfl[8][2];
#pragma unroll
            for (int nfp = 0; nfp < 4; nfp++) {
                uint32_t off = (uint32_t)((kfk * 16 + lrow16) * LDK
                                          + nfp * 16 + lsel * 8) * 2;
                uint32_t r0, r1, r2, r3;
                LDSM_T4(r0, r1, r2, r3, vhb + off);
                vfh[2 * nfp][0] = r0;     vfh[2 * nfp][1] = r1;
                vfh[2 * nfp + 1][0] = r2; vfh[2 * nfp + 1][1] = r3;
                LDSM_T4(r0, r1, r2, r3, vlb + off);
                vfl[2 * nfp][0] = r0;     vfl[2 * nfp][1] = r1;
                vfl[2 * nfp + 1][0] = r2; vfl[2 * nfp + 1][1] = r3;
            }
#pragma unroll
            for (int nf = 0; nf < 8; nf++) {
                MMA16816(o[nf], pah, vfh[nf][0], vfh[nf][1]);
                MMA16816(o[nf], pah, vfl[nf][0], vfl[nf][1]);
                MMA16816(o[nf], pal, vfh[nf][0], vfh[nf][1]);
            }
        }

        __syncthreads();
        if (kt + 2 < ntile)
            attn_issue(sbase, s, kt + 2, kvh, tid, kh_g, kl_g, vh_g, vl_g, pos, kpos);
    }

    float i0 = 1.f / l0, i1 = 1.f / l1;
    int g0 = q0 + w * 16 + rq;
    int g1 = g0 + 8;
#pragma unroll
    for (int nf = 0; nf < 8; nf++) {
        int col = h * HD + nf * 8 + cq * 2;
        uint32_t ph, pl;
        splitpack2(o[nf][0] * i0, o[nf][1] * i0, ph, pl);
        *reinterpret_cast<uint32_t*>(oh_g + (size_t)g0 * DQ + col) = ph;
        *reinterpret_cast<uint32_t*>(ol_g + (size_t)g0 * DQ + col) = pl;
        splitpack2(o[nf][2] * i1, o[nf][3] * i1, ph, pl);
        *reinterpret_cast<uint32_t*>(oh_g + (size_t)g1 * DQ + col) = ph;
        *reinterpret_cast<uint32_t*>(ol_g + (size_t)g1 * DQ + col) = pl;
    }
}

// ---------------------------------------------------------------------------
extern "C" void kernel_launch(void* const* d_in, const int* in_sizes, int n_in,
                              void* d_out, int out_size)
{
    const float* hidden    = (const float*)d_in[0];
    const int*   positions = (const int*)  d_in[1];
    const int*   sort_idx  = (const int*)  d_in[2];
    const float* q_proj_w  = (const float*)d_in[3];
    const float* o_proj_w  = (const float*)d_in[4];
    const float* k_w       = (const float*)d_in[5];
    const float* v_w       = (const float*)d_in[6];
    const float* q_norm_w  = (const float*)d_in[7];
    const float* k_norm_w  = (const float*)d_in[8];
    float* out = (float*)d_out;

    bf16 *hh, *hl, *oh, *ol, *qh, *ql, *kh2, *kl2, *vh, *vl;
    bf16 *wqh, *wql, *woh, *wol, *wkh, *wkl, *wvh, *wvl;
    float2* rope;
    cudaGetSymbolAddress((void**)&hh, g_hh);
    cudaGetSymbolAddress((void**)&hl, g_hl);
    cudaGetSymbolAddress((void**)&oh, g_oh);
    cudaGetSymbolAddress((void**)&ol, g_ol);
    cudaGetSymbolAddress((void**)&qh, g_qh);
    cudaGetSymbolAddress((void**)&ql, g_ql);
    cudaGetSymbolAddress((void**)&kh2, g_kh2);
    cudaGetSymbolAddress((void**)&kl2, g_kl2);
    cudaGetSymbolAddress((void**)&vh, g_vh);
    cudaGetSymbolAddress((void**)&vl, g_vl);
    cudaGetSymbolAddress((void**)&wqh, g_wq_h);
    cudaGetSymbolAddress((void**)&wql, g_wq_l);
    cudaGetSymbolAddress((void**)&woh, g_wo_h);
    cudaGetSymbolAddress((void**)&wol, g_wo_l);
    cudaGetSymbolAddress((void**)&wkh, g_wk_h);
    cudaGetSymbolAddress((void**)&wkl, g_wk_l);
    cudaGetSymbolAddress((void**)&wvh, g_wv_h);
    cudaGetSymbolAddress((void**)&wvl, g_wv_l);
    cudaGetSymbolAddress((void**)&rope, g_rope);

    cudaFuncSetAttribute(gemm_qkv, cudaFuncAttributeMaxDynamicSharedMemorySize, GEMM_SMEM);
    cudaFuncSetAttribute(gemm_o, cudaFuncAttributeMaxDynamicSharedMemorySize, GEMM_SMEM);
    cudaFuncSetAttribute(attn_mma, cudaFuncAttributeMaxDynamicSharedMemorySize, ASMEM);

    // 1) coalesced splits (no transposes) + RoPE table
    prep_split<<<PREP_BLOCKS, 256>>>(
        q_proj_w, o_proj_w, k_w, v_w, hidden, positions,
        wqh, wql, woh, wol, wkh, wkl, wvh, wvl, hh, hl, rope);

    // 2) q/k/v projections with fused RMSNorm/RoPE/split epilogues
    gemm_qkv<<<384, 256, GEMM_SMEM>>>(
        hh, hl, wqh, wql, wkh, wkl, wvh, wvl, sort_idx, rope,
        q_norm_w, k_norm_w, qh, ql, kh2, kl2, vh, vl);

    // 3) flash attention (3 CTAs/SM)
    attn_mma<<<dim3(NTOK / AQ, NH), 128, ASMEM>>>(
        qh, ql, kh2, kl2, vh, vl, positions, oh, ol);

    // 4) o-proj (routed)
    gemm_o<<<256, 256, GEMM_SMEM>>>(oh, ol, woh, wol, out, sort_idx);
}

// round 9
// speedup vs baseline: 2.1838x; 2.0748x over previous
#include <cuda_runtime.h>
#include <cuda_fp16.h>
#include <cstdint>
#include <math.h>

// Problem constants
#define NTOK 2048
#define HID 2048
#define NH 32
#define NKV 8
#define HD 64
#define NE 4
#define CHUNK (NTOK / NE)   // 512
#define DQ (NH * HD)        // 2048
#define DKV (NKV * HD)      // 512

typedef __half fp16;

// Scratch (single fp16 everywhere)
__device__ fp16 g_h[(size_t)NTOK * HID];
__device__ fp16 g_o[(size_t)NTOK * DQ];
__device__ fp16 g_qv[(size_t)NTOK * DQ];
__device__ fp16 g_kv[(size_t)NTOK * DKV];
__device__ fp16 g_vv[(size_t)NTOK * DKV];

__device__ fp16 g_wq[(size_t)NE * HID * DQ];   // [K][N] original layout
__device__ fp16 g_wo[(size_t)NE * DQ * HID];
__device__ fp16 g_wk[(size_t)HID * DKV];
__device__ fp16 g_wv[(size_t)HID * DKV];

__device__ float2 g_rope[(size_t)NTOK * 32];

// ---------------------------------------------------------------------------
__device__ __forceinline__ uint32_t smem_u32(const void* p) {
    uint32_t a;
    asm("{ .reg .u64 t; cvta.to.shared.u64 t, %1; cvt.u32.u64 %0, t; }"
        : "=r"(a) : "l"(p));
    return a;
}

#define CP16(dst, src) \
    asm volatile("cp.async.cg.shared.global [%0], [%1], 16;" \
        :: "r"(dst), "l"(src) : "memory")
#define CP_COMMIT() asm volatile("cp.async.commit_group;" ::: "memory")

#define MMA16816(d, a, b0, b1) \
    asm volatile("mma.sync.aligned.m16n8k16.row.col.f32.f16.f16.f32 " \
        "{%0,%1,%2,%3}, {%4,%5,%6,%7}, {%8,%9}, {%0,%1,%2,%3};" \
        : "+f"((d)[0]), "+f"((d)[1]), "+f"((d)[2]), "+f"((d)[3]) \
        : "r"((a)[0]), "r"((a)[1]), "r"((a)[2]), "r"((a)[3]), "r"(b0), "r"(b1))

#define LDSM_4(r0, r1, r2, r3, a) \
    asm volatile("ldmatrix.sync.aligned.m8n8.x4.shared.b16 {%0,%1,%2,%3}, [%4];" \
        : "=r"(r0), "=r"(r1), "=r"(r2), "=r"(r3) : "r"(a))

#define LDSM_T4(r0, r1, r2, r3, a) \
    asm volatile("ldmatrix.sync.aligned.m8n8.x4.trans.shared.b16 {%0,%1,%2,%3}, [%4];" \
        : "=r"(r0), "=r"(r1), "=r"(r2), "=r"(r3) : "r"(a))

__device__ __forceinline__ uint32_t pack_half2(float a, float b) {
    __half2 h = __floats2half2_rn(a, b);
    return *reinterpret_cast<uint32_t*>(&h);
}

// ---------------------------------------------------------------------------
// Prep: coalesced fp32->fp16 converts + RoPE table.
// ---------------------------------------------------------------------------
__device__ __forceinline__ void conv4(const float* __restrict__ X,
                                      fp16* __restrict__ H, int i) {
    float4 v = reinterpret_cast<const float4*>(X)[i];
    uint2 o;
    o.x = pack_half2(v.x, v.y);
    o.y = pack_half2(v.z, v.w);
    reinterpret_cast<uint2*>(H)[i] = o;
}

#define PB_Q 16384
#define PB_O 16384
#define PB_K 1024
#define PB_V 1024
#define PB_H 4096
#define PB_R 256
#define PREP_BLOCKS (PB_Q + PB_O + PB_K + PB_V + PB_H + PB_R)

__global__ void __launch_bounds__(256) prep_split(
    const float* __restrict__ q_proj_w, const float* __restrict__ o_proj_w,
    const float* __restrict__ k_w, const float* __restrict__ v_w,
    const float* __restrict__ hidden, const int* __restrict__ pos,
    fp16* __restrict__ wq, fp16* __restrict__ wo,
    fp16* __restrict__ wk, fp16* __restrict__ wv,
    fp16* __restrict__ h, float2* __restrict__ rope)
{
    int b = blockIdx.x;
    int tid = threadIdx.x;
    if (b < PB_Q) {
        conv4(q_proj_w, wq, b * 256 + tid);
    } else if (b < PB_Q + PB_O) {
        conv4(o_proj_w, wo, (b - PB_Q) * 256 + tid);
    } else if (b < PB_Q + PB_O + PB_K) {
        conv4(k_w, wk, (b - PB_Q - PB_O) * 256 + tid);
    } else if (b < PB_Q + PB_O + PB_K + PB_V) {
        conv4(v_w, wv, (b - PB_Q - PB_O - PB_K) * 256 + tid);
    } else if (b < PB_Q + PB_O + PB_K + PB_V + PB_H) {
        conv4(hidden, h, (b - PB_Q - PB_O - PB_K - PB_V) * 256 + tid);
    } else {
        int i = (b - PB_Q - PB_O - PB_K - PB_V - PB_H) * 256 + tid;
        int t = i >> 5;
        int c = i & 31;
        float inv = powf(10000.0f, -(float)c * (1.0f / 32.0f));
        float s, cs;
        sincosf((float)pos[t] * inv, &s, &cs);
        rope[i] = make_float2(cs, s);
    }
}

// ---------------------------------------------------------------------------
// fp16 mma.sync GEMM mainloop (128x128 tile), B from [K][N] via ldmatrix.trans.
// ---------------------------------------------------------------------------
#define LDA 40
#define LDB 136
#define A_E (128 * LDA)                // 5120 elements
#define B_E (32 * LDB)                 // 4352 elements
#define STAGE_EL (A_E + B_E)           // 9472 el = 18944 B
#define GEMM_SMEM (1024 + 2 * STAGE_EL * 2)   // 38912

__device__ __forceinline__ void issue_tile(
    uint32_t sB, int s, int kb,
    const fp16* __restrict__ Ag, const fp16* __restrict__ Bg,
    const int* __restrict__ rows, int n0, int K, int Nd, int tid)
{
#pragma unroll
    for (int rep = 0; rep < 2; rep++) {
        int f = tid + rep * 256;               // 0..511
        // A: row m, 16B chunk q (32 fp16/row = 4 chunks)
        int m = f >> 2;
        int q = f & 3;
        uint32_t adst = sB + (uint32_t)s * (STAGE_EL * 2) + m * (LDA * 2) + q * 16;
        CP16(adst, Ag + (size_t)rows[m] * K + kb + q * 8);
        // B: row kk, 16B chunk seg (128 fp16/row = 16 chunks)
        int kk = f >> 4;
        int seg = f & 15;
        uint32_t bdst = sB + (uint32_t)s * (STAGE_EL * 2) + (A_E + kk * LDB) * 2
                      + seg * 16;
        CP16(bdst, Bg + (size_t)(kb + kk) * Nd + n0 + seg * 8);
    }
}

__device__ __forceinline__ void gemm_mainloop(
    const fp16* __restrict__ Ag, const fp16* __restrict__ Bg,
    const int* __restrict__ idx,
    int K, int Nd, int m0, int n0, int zchunk, char* smc,
    float acc[2][8][4])
{
    int* rows = (int*)smc;
    const uint32_t sB = smem_u32(smc + 1024);
    const int tid = threadIdx.x;
    const int wid = tid >> 5;
    const int lane = tid & 31;

    if (tid < 128) {
        int lr = zchunk + m0 + tid;
        rows[tid] = idx ? idx[lr] : lr;
    }
    __syncthreads();

    const int wm = (wid & 3) * 32;
    const int wn = (wid >> 2) * 64;
    const uint32_t lnA = ((((lane >> 3) & 1) * 8 + (lane & 7)) * LDA + (lane >> 4) * 8) * 2;
    const uint32_t lnBT = ((lane & 15) * LDB + (lane >> 4) * 8) * 2;

#pragma unroll
    for (int a = 0; a < 2; a++)
#pragma unroll
        for (int b = 0; b < 8; b++)
#pragma unroll
            for (int c = 0; c < 4; c++) acc[a][b][c] = 0.f;

    const int nkt = K / 32;
    issue_tile(sB, 0, 0, Ag, Bg, rows, n0, K, Nd, tid); CP_COMMIT();
    issue_tile(sB, 1, 32, Ag, Bg, rows, n0, K, Nd, tid); CP_COMMIT();

    for (int kt = 0; kt < nkt; kt++) {
        if (kt + 1 < nkt) asm volatile("cp.async.wait_group 1;" ::: "memory");
        else              asm volatile("cp.async.wait_group 0;" ::: "memory");
        __syncthreads();

        const int s = kt & 1;
        const uint32_t sb_s = sB + (uint32_t)s * (STAGE_EL * 2);
        const uint32_t bb_s = sb_s + (uint32_t)A_E * 2;

#pragma unroll
        for (int ks = 0; ks < 32; ks += 16) {
            uint32_t ah[2][4];
            uint32_t abase = sb_s + (uint32_t)(wm * LDA + ks) * 2 + lnA;
#pragma unroll
            for (int mi = 0; mi < 2; mi++)
                LDSM_4(ah[mi][0], ah[mi][1], ah[mi][2], ah[mi][3],
                       abase + mi * (16 * LDA * 2));
#pragma unroll
            for (int np = 0; np < 4; np++) {
                uint32_t boff = bb_s + (uint32_t)(ks * LDB + wn + np * 16) * 2 + lnBT;
                uint32_t b0, b1, b2, b3;
                LDSM_T4(b0, b1, b2, b3, boff);
#pragma unroll
                for (int mi = 0; mi < 2; mi++) {
                    MMA16816(acc[mi][2 * np], ah[mi], b0, b1);
                    MMA16816(acc[mi][2 * np + 1], ah[mi], b2, b3);
                }
            }
        }
        __syncthreads();
        if (kt + 2 < nkt) {
            issue_tile(sB, s, (kt + 2) * 32, Ag, Bg, rows, n0, K, Nd, tid);
            CP_COMMIT();
        }
    }
}

// Epilogue: fused RMSNorm + NeoX RoPE (table) + fp16 convert (warp tile = one head)
__device__ __forceinline__ void epi_norm_rope(
    float acc[2][8][4], const int* __restrict__ rows,
    const float* __restrict__ w, const float2* __restrict__ rope, float sc,
    fp16* __restrict__ Out, int outstride, int headcol0)
{
    const int lane = threadIdx.x & 31;
    const int wid = threadIdx.x >> 5;
    const int wm = (wid & 3) * 32;
    const int rq = lane >> 2, cq = lane & 3;

#pragma unroll
    for (int mi = 0; mi < 2; mi++) {
#pragma unroll
        for (int hf = 0; hf < 2; hf++) {
            int r = wm + mi * 16 + rq + hf * 8;
            int gr = rows[r];
            float ss = 0.f;
#pragma unroll
            for (int nf = 0; nf < 8; nf++) {
                float a = acc[mi][nf][hf * 2], b = acc[mi][nf][hf * 2 + 1];
                ss += a * a + b * b;
            }
            ss += __shfl_xor_sync(0xffffffff, ss, 1);
            ss += __shfl_xor_sync(0xffffffff, ss, 2);
            float rn = rsqrtf(ss * (1.0f / 64.0f) + 1e-6f) * sc;
            const float2* rt = rope + (size_t)gr * 32;
#pragma unroll
            for (int nf = 0; nf < 4; nf++) {
                float o1[2], o2[2];
#pragma unroll
                for (int par = 0; par < 2; par++) {
                    int c = nf * 8 + cq * 2 + par;
                    float y1 = acc[mi][nf][hf * 2 + par] * rn * w[c];
                    float y2 = acc[mi][nf + 4][hf * 2 + par] * rn * w[c + 32];
                    float2 cs = rt[c];
                    o1[par] = y1 * cs.x - y2 * cs.y;
                    o2[par] = y2 * cs.x + y1 * cs.y;
                }
                size_t base = (size_t)gr * outstride + headcol0 + nf * 8 + cq * 2;
                *reinterpret_cast<uint32_t*>(Out + base) = pack_half2(o1[0], o1[1]);
                *reinterpret_cast<uint32_t*>(Out + base + 32) = pack_half2(o2[0], o2[1]);
            }
        }
    }
}

// Epilogue: plain fp16 convert (v)
__device__ __forceinline__ void epi_conv(
    float acc[2][8][4], const int* __restrict__ rows,
    fp16* __restrict__ Out, int outstride, int col0)
{
    const int lane = threadIdx.x & 31;
    const int wid = threadIdx.x >> 5;
    const int wm = (wid & 3) * 32;
    const int wn = (wid >> 2) * 64;
    const int rq = lane >> 2, cq = lane & 3;
#pragma unroll
    for (int mi = 0; mi < 2; mi++) {
        int r = wm + mi * 16 + rq;
        size_t gr0 = (size_t)rows[r];
        size_t gr1 = (size_t)rows[r + 8];
#pragma unroll
        for (int nf = 0; nf < 8; nf++) {
            int col = col0 + wn + nf * 8 + cq * 2;
            *reinterpret_cast<uint32_t*>(Out + gr0 * outstride + col) =
                pack_half2(acc[mi][nf][0], acc[mi][nf][1]);
            *reinterpret_cast<uint32_t*>(Out + gr1 * outstride + col) =
                pack_half2(acc[mi][nf][2], acc[mi][nf][3]);
        }
    }
}

// Merged q-proj (bid<256, routed) + k-proj + v-proj; fused norm/rope epilogues.
__global__ void __launch_bounds__(256, 2) gemm_qkv(
    const fp16* __restrict__ h, const fp16* __restrict__ wq,
    const fp16* __restrict__ wk, const fp16* __restrict__ wv,
    const int* __restrict__ sort_idx, const float2* __restrict__ rope,
    const float* __restrict__ q_norm_w, const float* __restrict__ k_norm_w,
    fp16* __restrict__ qv, fp16* __restrict__ kv, fp16* __restrict__ vv)
{
    extern __shared__ char smc[];
    float acc[2][8][4];
    int* rows = (int*)smc;
    int bid = blockIdx.x;
    const int wn = ((threadIdx.x >> 5) >> 2) * 64;

    if (bid < 256) {
        int x = bid & 15, y = (bid >> 4) & 3, z = bid >> 6;
        gemm_mainloop(h, wq + (size_t)z * HID * DQ,
                      sort_idx, HID, DQ, y * 128, x * 128, z * CHUNK, smc, acc);
        epi_norm_rope(acc, rows, q_norm_w, rope, 0.125f, qv, DQ, x * 128 + wn);
    } else {
        int bb = bid - 256;
        int x = bb & 7, y = bb >> 3;
        if (x < 4) {
            gemm_mainloop(h, wk, nullptr, HID, DKV, y * 128, x * 128, 0, smc, acc);
            epi_norm_rope(acc, rows, k_norm_w, rope, 1.0f, kv, DKV, x * 128 + wn);
        } else {
            gemm_mainloop(h, wv, nullptr, HID, DKV, y * 128, (x - 4) * 128, 0, smc, acc);
            epi_conv(acc, rows, vv, DKV, (x - 4) * 128);
        }
    }
}

// o-proj (routed), fp32 output
__global__ void __launch_bounds__(256, 2) gemm_o(
    const fp16* __restrict__ o, const fp16* __restrict__ wo,
    float* __restrict__ out, const int* __restrict__ sort_idx)
{
    extern __shared__ char smc[];
    float acc[2][8][4];
    int* rows = (int*)smc;
    int bid = blockIdx.x;
    int x = bid & 15, y = (bid >> 4) & 3, z = bid >> 6;
    gemm_mainloop(o, wo + (size_t)z * DQ * HID,
                  sort_idx, DQ, HID, y * 128, x * 128, z * CHUNK, smc, acc);

    const int lane = threadIdx.x & 31;
    const int wid = threadIdx.x >> 5;
    const int wm = (wid & 3) * 32;
    const int wn = (wid >> 2) * 64;
    const int rq = lane >> 2;
    const int cq = (lane & 3) * 2;
#pragma unroll
    for (int mi = 0; mi < 2; mi++) {
        int r = wm + mi * 16 + rq;
        size_t gr0 = (size_t)rows[r];
        size_t gr1 = (size_t)rows[r + 8];
#pragma unroll
        for (int ni = 0; ni < 8; ni++) {
            int col = x * 128 + wn + ni * 8 + cq;
            *reinterpret_cast<float2*>(&out[gr0 * HID + col]) =
                make_float2(acc[mi][ni][0], acc[mi][ni][1]);
            *reinterpret_cast<float2*>(&out[gr1 * HID + col]) =
                make_float2(acc[mi][ni][2], acc[mi][ni][3]);
        }
    }
}

// ---------------------------------------------------------------------------
// fp16 flash attention, AQ=64 / 128 threads / 3 CTAs per SM.
// ---------------------------------------------------------------------------
#define AQ 64
#define AK 64
#define LDK 72
#define KSM (AK * LDK)     // 4608 elements
#define ASMEM (4 * KSM * 2 + 2 * AK * 4)   // 37376

__device__ __forceinline__ void attn_issue(
    uint32_t sbase, int s, int kt, int kvh, int tid,
    const fp16* __restrict__ k_g, const fp16* __restrict__ v_g,
    const int* __restrict__ pos, int* __restrict__ kpos_sm)
{
#pragma unroll
    for (int i = 0; i < 8; i++) {
        int f = tid + i * 128;          // 0..1023
        int arr = f >> 9;               // 0=K, 1=V
        int r = (f >> 3) & 63;
        int seg = f & 7;
        const fp16* src = arr ? v_g : k_g;
        uint32_t dst = sbase + (uint32_t)((s * 2 + arr) * KSM + r * LDK) * 2
                     + seg * 16;
        CP16(dst, src + (size_t)(kt * AK + r) * DKV + (size_t)kvh * HD + seg * 8);
    }
    if (tid < AK) kpos_sm[s * AK + tid] = pos[kt * AK + tid];
    CP_COMMIT();
}

__global__ void __launch_bounds__(128, 3) attn_mma(
    const fp16* __restrict__ q_g, const fp16* __restrict__ k_g,
    const fp16* __restrict__ v_g, const int* __restrict__ pos,
    fp16* __restrict__ o_g)
{
    extern __shared__ char sm[];
    const uint32_t sbase = smem_u32(sm);
    int* kpos = (int*)(sm + (size_t)4 * KSM * 2);

    const int tid = threadIdx.x;
    const int w = tid >> 5;
    const int l = tid & 31;
    const int qt = gridDim.x - 1 - blockIdx.x;   // heavy tiles first
    const int h = blockIdx.y;
    const int kvh = h >> 2;
    const int q0 = qt * AQ;
    const int ntile = qt + 1;

    attn_issue(sbase, 0, 0, kvh, tid, k_g, v_g, pos, kpos);
    attn_issue(sbase, 1, 1 < ntile ? 1 : 0, kvh, tid, k_g, v_g, pos, kpos);

    const int rq = l >> 2;
    const int cq = l & 3;
    const int row0 = w * 16 + rq;

    // Q fragments straight from gmem
    uint32_t qf[4][4];
    {
        const fp16* qb = q_g + (size_t)(q0 + row0) * DQ + h * HD;
#pragma unroll
        for (int kf = 0; kf < 4; kf++) {
            int e0 = kf * 16 + cq * 2;
            qf[kf][0] = *reinterpret_cast<const uint32_t*>(qb + e0);
            qf[kf][1] = *reinterpret_cast<const uint32_t*>(qb + 8 * DQ + e0);
            qf[kf][2] = *reinterpret_cast<const uint32_t*>(qb + e0 + 8);
            qf[kf][3] = *reinterpret_cast<const uint32_t*>(qb + 8 * DQ + e0 + 8);
        }
    }
    const int qp0 = pos[q0 + row0];
    const int qp1 = pos[q0 + row0 + 8];

    float o[8][4];
#pragma unroll
    for (int nf = 0; nf < 8; nf++)
#pragma unroll
        for (int e = 0; e < 4; e++) o[nf][e] = 0.f;
    float m0 = -1e30f, m1 = -1e30f, l0 = 0.f, l1 = 0.f;

    const int lrow16 = l & 15;
    const int lsel = l >> 4;
    const uint32_t lnK = (((l >> 4) * 8 + (l & 7)) * LDK + ((l >> 3) & 1) * 8) * 2;

    for (int kt = 0; kt < ntile; kt++) {
        if (kt + 1 < ntile) asm volatile("cp.async.wait_group 1;" ::: "memory");
        else                asm volatile("cp.async.wait_group 0;" ::: "memory");
        __syncthreads();

        const int s = kt & 1;
        const uint32_t kb = sbase + (uint32_t)((s * 2 + 0) * KSM) * 2;
        const uint32_t vb = sbase + (uint32_t)((s * 2 + 1) * KSM) * 2;

        float sv[8][4];
#pragma unroll
        for (int nf = 0; nf < 8; nf++)
#pragma unroll
            for (int e = 0; e < 4; e++) sv[nf][e] = 0.f;

        // S = Q K^T
#pragma unroll
        for (int kf = 0; kf < 4; kf++) {
#pragma unroll
            for (int np = 0; np < 4; np++) {
                uint32_t koff = kb + (uint32_t)(np * 16 * LDK) * 2 + kf * 32 + lnK;
                uint32_t b0, b1, b2, b3;
                LDSM_4(b0, b1, b2, b3, koff);
                MMA16816(sv[2 * np], qf[kf], b0, b1);
                MMA16816(sv[2 * np + 1], qf[kf], b2, b3);
            }
        }

        if (kt == qt) {   // only diagonal tile crosses the mask
            const int* kp = kpos + s * AK;
#pragma unroll
            for (int nf = 0; nf < 8; nf++) {
                int c = nf * 8 + cq * 2;
                int k0 = kp[c], k1 = kp[c + 1];
                if (k0 > qp0) sv[nf][0] = -1e30f;
                if (k1 > qp0) sv[nf][1] = -1e30f;
                if (k0 > qp1) sv[nf][2] = -1e30f;
                if (k1 > qp1) sv[nf][3] = -1e30f;
            }
        }

        float mt0 = -1e30f, mt1 = -1e30f;
#pragma unroll
        for (int nf = 0; nf < 8; nf++) {
            mt0 = fmaxf(mt0, fmaxf(sv[nf][0], sv[nf][1]));
            mt1 = fmaxf(mt1, fmaxf(sv[nf][2], sv[nf][3]));
        }
        mt0 = fmaxf(mt0, __shfl_xor_sync(0xffffffff, mt0, 1));
        mt0 = fmaxf(mt0, __shfl_xor_sync(0xffffffff, mt0, 2));
        mt1 = fmaxf(mt1, __shfl_xor_sync(0xffffffff, mt1, 1));
        mt1 = fmaxf(mt1, __shfl_xor_sync(0xffffffff, mt1, 2));
        float mn0 = fmaxf(m0, mt0), mn1 = fmaxf(m1, mt1);
        float a0 = __expf(m0 - mn0), a1 = __expf(m1 - mn1);
        m0 = mn0; m1 = mn1;
#pragma unroll
        for (int nf = 0; nf < 8; nf++) {
            o[nf][0] *= a0; o[nf][1] *= a0;
            o[nf][2] *= a1; o[nf][3] *= a1;
        }
        float rs0 = 0.f, rs1 = 0.f;
#pragma unroll
        for (int nf = 0; nf < 8; nf++) {
            sv[nf][0] = __expf(sv[nf][0] - mn0); rs0 += sv[nf][0];
            sv[nf][1] = __expf(sv[nf][1] - mn0); rs0 += sv[nf][1];
            sv[nf][2] = __expf(sv[nf][2] - mn1); rs1 += sv[nf][2];
            sv[nf][3] = __expf(sv[nf][3] - mn1); rs1 += sv[nf][3];
        }
        rs0 += __shfl_xor_sync(0xffffffff, rs0, 1);
        rs0 += __shfl_xor_sync(0xffffffff, rs0, 2);
        rs1 += __shfl_xor_sync(0xffffffff, rs1, 1);
        rs1 += __shfl_xor_sync(0xffffffff, rs1, 2);
        l0 = l0 * a0 + rs0;
        l1 = l1 * a1 + rs1;

        // O += P V
#pragma unroll
        for (int kfk = 0; kfk < 4; kfk++) {
            uint32_t pa[4];
            pa[0] = pack_half2(sv[2 * kfk][0], sv[2 * kfk][1]);
            pa[1] = pack_half2(sv[2 * kfk][2], sv[2 * kfk][3]);
            pa[2] = pack_half2(sv[2 * kfk + 1][0], sv[2 * kfk + 1][1]);
            pa[3] = pack_half2(sv[2 * kfk + 1][2], sv[2 * kfk + 1][3]);

            uint32_t vf[8][2];
#pragma unroll
            for (int nfp = 0; nfp < 4; nfp++) {
                uint32_t off = (uint32_t)((kfk * 16 + lrow16) * LDK
                                          + nfp * 16 + lsel * 8) * 2;
                uint32_t r0, r1, r2, r3;
                LDSM_T4(r0, r1, r2, r3, vb + off);
                vf[2 * nfp][0] = r0;     vf[2 * nfp][1] = r1;
                vf[2 * nfp + 1][0] = r2; vf[2 * nfp + 1][1] = r3;
            }
#pragma unroll
            for (int nf = 0; nf < 8; nf++)
                MMA16816(o[nf], pa, vf[nf][0], vf[nf][1]);
        }

        __syncthreads();
        if (kt + 2 < ntile)
            attn_issue(sbase, s, kt + 2, kvh, tid, k_g, v_g, pos, kpos);
    }

    float i0 = 1.f / l0, i1 = 1.f / l1;
    int g0 = q0 + w * 16 + rq;
    int g1 = g0 + 8;
#pragma unroll
    for (int nf = 0; nf < 8; nf++) {
        int col = h * HD + nf * 8 + cq * 2;
        *reinterpret_cast<uint32_t*>(o_g + (size_t)g0 * DQ + col) =
            pack_half2(o[nf][0] * i0, o[nf][1] * i0);
        *reinterpret_cast<uint32_t*>(o_g + (size_t)g1 * DQ + col) =
            pack_half2(o[nf][2] * i1, o[nf][3] * i1);
    }
}

// ---------------------------------------------------------------------------
extern "C" void kernel_launch(void* const* d_in, const int* in_sizes, int n_in,
                              void* d_out, int out_size)
{
    const float* hidden    = (const float*)d_in[0];
    const int*   positions = (const int*)  d_in[1];
    const int*   sort_idx  = (const int*)  d_in[2];
    const float* q_proj_w  = (const float*)d_in[3];
    const float* o_proj_w  = (const float*)d_in[4];
    const float* k_w       = (const float*)d_in[5];
    const float* v_w       = (const float*)d_in[6];
    const float* q_norm_w  = (const float*)d_in[7];
    const float* k_norm_w  = (const float*)d_in[8];
    float* out = (float*)d_out;

    fp16 *h, *o, *qv, *kv, *vv, *wq, *wo, *wk, *wv;
    float2* rope;
    cudaGetSymbolAddress((void**)&h, g_h);
    cudaGetSymbolAddress((void**)&o, g_o);
    cudaGetSymbolAddress((void**)&qv, g_qv);
    cudaGetSymbolAddress((void**)&kv, g_kv);
    cudaGetSymbolAddress((void**)&vv, g_vv);
    cudaGetSymbolAddress((void**)&wq, g_wq);
    cudaGetSymbolAddress((void**)&wo, g_wo);
    cudaGetSymbolAddress((void**)&wk, g_wk);
    cudaGetSymbolAddress((void**)&wv, g_wv);
    cudaGetSymbolAddress((void**)&rope, g_rope);

    cudaFuncSetAttribute(gemm_qkv, cudaFuncAttributeMaxDynamicSharedMemorySize, GEMM_SMEM);
    cudaFuncSetAttribute(gemm_o, cudaFuncAttributeMaxDynamicSharedMemorySize, GEMM_SMEM);
    cudaFuncSetAttribute(attn_mma, cudaFuncAttributeMaxDynamicSharedMemorySize, ASMEM);

    // 1) coalesced fp32->fp16 converts + RoPE table
    prep_split<<<PREP_BLOCKS, 256>>>(
        q_proj_w, o_proj_w, k_w, v_w, hidden, positions,
        wq, wo, wk, wv, h, rope);

    // 2) q/k/v projections with fused RMSNorm/RoPE epilogues
    gemm_qkv<<<384, 256, GEMM_SMEM>>>(
        h, wq, wk, wv, sort_idx, rope, q_norm_w, k_norm_w, qv, kv, vv);

    // 3) flash attention
    attn_mma<<<dim3(NTOK / AQ, NH), 128, ASMEM>>>(qv, kv, vv, positions, o);

    // 4) o-proj (routed)
    gemm_o<<<256, 256, GEMM_SMEM>>>(o, wo, out, sort_idx);
}

// round 10
// speedup vs baseline: 2.3437x; 1.0732x over previous
#include <cuda_runtime.h>
#include <cuda_fp16.h>
#include <cstdint>
#include <math.h>

// Problem constants
#define NTOK 2048
#define HID 2048
#define NH 32
#define NKV 8
#define HD 64
#define NE 4
#define CHUNK (NTOK / NE)   // 512
#define DQ (NH * HD)        // 2048
#define DKV (NKV * HD)      // 512

typedef __half fp16;

// Scratch (single fp16 everywhere)
__device__ fp16 g_h[(size_t)NTOK * HID];
__device__ fp16 g_o[(size_t)NTOK * DQ];
__device__ fp16 g_qv[(size_t)NTOK * DQ];
__device__ fp16 g_kv[(size_t)NTOK * DKV];
__device__ fp16 g_vv[(size_t)NTOK * DKV];

__device__ fp16 g_wq[(size_t)NE * HID * DQ];   // [K][N] original layout
__device__ fp16 g_wo[(size_t)NE * DQ * HID];
__device__ fp16 g_wk[(size_t)HID * DKV];
__device__ fp16 g_wv[(size_t)HID * DKV];

__device__ float2 g_rope[(size_t)NTOK * 32];

// ---------------------------------------------------------------------------
__device__ __forceinline__ uint32_t smem_u32(const void* p) {
    uint32_t a;
    asm("{ .reg .u64 t; cvta.to.shared.u64 t, %1; cvt.u32.u64 %0, t; }"
        : "=r"(a) : "l"(p));
    return a;
}

#define CP16(dst, src) \
    asm volatile("cp.async.cg.shared.global [%0], [%1], 16;" \
        :: "r"(dst), "l"(src) : "memory")
#define CP_COMMIT() asm volatile("cp.async.commit_group;" ::: "memory")
#define CP_WAIT(n) asm volatile("cp.async.wait_group %0;" :: "n"(n) : "memory")

#define MMA16816(d, a, b0, b1) \
    asm volatile("mma.sync.aligned.m16n8k16.row.col.f32.f16.f16.f32 " \
        "{%0,%1,%2,%3}, {%4,%5,%6,%7}, {%8,%9}, {%0,%1,%2,%3};" \
        : "+f"((d)[0]), "+f"((d)[1]), "+f"((d)[2]), "+f"((d)[3]) \
        : "r"((a)[0]), "r"((a)[1]), "r"((a)[2]), "r"((a)[3]), "r"(b0), "r"(b1))

#define LDSM_4(r0, r1, r2, r3, a) \
    asm volatile("ldmatrix.sync.aligned.m8n8.x4.shared.b16 {%0,%1,%2,%3}, [%4];" \
        : "=r"(r0), "=r"(r1), "=r"(r2), "=r"(r3) : "r"(a))

#define LDSM_T4(r0, r1, r2, r3, a) \
    asm volatile("ldmatrix.sync.aligned.m8n8.x4.trans.shared.b16 {%0,%1,%2,%3}, [%4];" \
        : "=r"(r0), "=r"(r1), "=r"(r2), "=r"(r3) : "r"(a))

__device__ __forceinline__ uint32_t pack_half2(float a, float b) {
    __half2 h = __floats2half2_rn(a, b);
    return *reinterpret_cast<uint32_t*>(&h);
}

// ---------------------------------------------------------------------------
// Prep: coalesced fp32->fp16 converts + RoPE table.
// ---------------------------------------------------------------------------
__device__ __forceinline__ void conv4(const float* __restrict__ X,
                                      fp16* __restrict__ H, int i) {
    float4 v = reinterpret_cast<const float4*>(X)[i];
    uint2 o;
    o.x = pack_half2(v.x, v.y);
    o.y = pack_half2(v.z, v.w);
    reinterpret_cast<uint2*>(H)[i] = o;
}

#define PB_Q 16384
#define PB_O 16384
#define PB_K 1024
#define PB_V 1024
#define PB_H 4096
#define PB_R 256
#define PREP_BLOCKS (PB_Q + PB_O + PB_K + PB_V + PB_H + PB_R)

__global__ void __launch_bounds__(256) prep_split(
    const float* __restrict__ q_proj_w, const float* __restrict__ o_proj_w,
    const float* __restrict__ k_w, const float* __restrict__ v_w,
    const float* __restrict__ hidden, const int* __restrict__ pos,
    fp16* __restrict__ wq, fp16* __restrict__ wo,
    fp16* __restrict__ wk, fp16* __restrict__ wv,
    fp16* __restrict__ h, float2* __restrict__ rope)
{
    int b = blockIdx.x;
    int tid = threadIdx.x;
    if (b < PB_Q) {
        conv4(q_proj_w, wq, b * 256 + tid);
    } else if (b < PB_Q + PB_O) {
        conv4(o_proj_w, wo, (b - PB_Q) * 256 + tid);
    } else if (b < PB_Q + PB_O + PB_K) {
        conv4(k_w, wk, (b - PB_Q - PB_O) * 256 + tid);
    } else if (b < PB_Q + PB_O + PB_K + PB_V) {
        conv4(v_w, wv, (b - PB_Q - PB_O - PB_K) * 256 + tid);
    } else if (b < PB_Q + PB_O + PB_K + PB_V + PB_H) {
        conv4(hidden, h, (b - PB_Q - PB_O - PB_K - PB_V) * 256 + tid);
    } else {
        int i = (b - PB_Q - PB_O - PB_K - PB_V - PB_H) * 256 + tid;
        int t = i >> 5;
        int c = i & 31;
        float inv = powf(10000.0f, -(float)c * (1.0f / 32.0f));
        float s, cs;
        sincosf((float)pos[t] * inv, &s, &cs);
        rope[i] = make_float2(cs, s);
    }
}

// ---------------------------------------------------------------------------
// fp16 mma.sync GEMM mainloop (128x128 tile), 3-stage cp.async pipeline.
// B from [K][N] via ldmatrix.trans.
// ---------------------------------------------------------------------------
#define LDA 40
#define LDB 136
#define A_E (128 * LDA)                // 5120 elements
#define B_E (32 * LDB)                 // 4352 elements
#define STAGE_EL (A_E + B_E)           // 9472 el = 18944 B
#define NSTG 3
#define GEMM_SMEM (1024 + NSTG * STAGE_EL * 2)   // 57856

__device__ __forceinline__ void issue_tile(
    uint32_t sB, int s, int kb,
    const fp16* __restrict__ Ag, const fp16* __restrict__ Bg,
    const int* __restrict__ rows, int n0, int K, int Nd, int tid)
{
#pragma unroll
    for (int rep = 0; rep < 2; rep++) {
        int f = tid + rep * 256;               // 0..511
        int m = f >> 2;
        int q = f & 3;
        uint32_t adst = sB + (uint32_t)s * (STAGE_EL * 2) + m * (LDA * 2) + q * 16;
        CP16(adst, Ag + (size_t)rows[m] * K + kb + q * 8);
        int kk = f >> 4;
        int seg = f & 15;
        uint32_t bdst = sB + (uint32_t)s * (STAGE_EL * 2) + (A_E + kk * LDB) * 2
                      + seg * 16;
        CP16(bdst, Bg + (size_t)(kb + kk) * Nd + n0 + seg * 8);
    }
}

__device__ __forceinline__ void gemm_mainloop(
    const fp16* __restrict__ Ag, const fp16* __restrict__ Bg,
    const int* __restrict__ idx,
    int K, int Nd, int m0, int n0, int zchunk, char* smc,
    float acc[2][8][4])
{
    int* rows = (int*)smc;
    const uint32_t sB = smem_u32(smc + 1024);
    const int tid = threadIdx.x;
    const int wid = tid >> 5;
    const int lane = tid & 31;

    if (tid < 128) {
        int lr = zchunk + m0 + tid;
        rows[tid] = idx ? idx[lr] : lr;
    }
    __syncthreads();

    const int wm = (wid & 3) * 32;
    const int wn = (wid >> 2) * 64;
    const uint32_t lnA = ((((lane >> 3) & 1) * 8 + (lane & 7)) * LDA + (lane >> 4) * 8) * 2;
    const uint32_t lnBT = ((lane & 15) * LDB + (lane >> 4) * 8) * 2;

#pragma unroll
    for (int a = 0; a < 2; a++)
#pragma unroll
        for (int b = 0; b < 8; b++)
#pragma unroll
            for (int c = 0; c < 4; c++) acc[a][b][c] = 0.f;

    const int nkt = K / 32;   // >= 16 for all our shapes
    issue_tile(sB, 0, 0, Ag, Bg, rows, n0, K, Nd, tid); CP_COMMIT();
    issue_tile(sB, 1, 32, Ag, Bg, rows, n0, K, Nd, tid); CP_COMMIT();
    issue_tile(sB, 2, 64, Ag, Bg, rows, n0, K, Nd, tid); CP_COMMIT();

    int s = 0;
    for (int kt = 0; kt < nkt; kt++) {
        if (kt < nkt - 2)      CP_WAIT(2);
        else if (kt == nkt - 2) CP_WAIT(1);
        else                    CP_WAIT(0);
        __syncthreads();

        const uint32_t sb_s = sB + (uint32_t)s * (STAGE_EL * 2);
        const uint32_t bb_s = sb_s + (uint32_t)A_E * 2;

#pragma unroll
        for (int ks = 0; ks < 32; ks += 16) {
            uint32_t ah[2][4];
            uint32_t abase = sb_s + (uint32_t)(wm * LDA + ks) * 2 + lnA;
#pragma unroll
            for (int mi = 0; mi < 2; mi++)
                LDSM_4(ah[mi][0], ah[mi][1], ah[mi][2], ah[mi][3],
                       abase + mi * (16 * LDA * 2));
#pragma unroll
            for (int np = 0; np < 4; np++) {
                uint32_t boff = bb_s + (uint32_t)(ks * LDB + wn + np * 16) * 2 + lnBT;
                uint32_t b0, b1, b2, b3;
                LDSM_T4(b0, b1, b2, b3, boff);
#pragma unroll
                for (int mi = 0; mi < 2; mi++) {
                    MMA16816(acc[mi][2 * np], ah[mi], b0, b1);
                    MMA16816(acc[mi][2 * np + 1], ah[mi], b2, b3);
                }
            }
        }
        __syncthreads();
        if (kt + NSTG < nkt) {
            issue_tile(sB, s, (kt + NSTG) * 32, Ag, Bg, rows, n0, K, Nd, tid);
            CP_COMMIT();
        }
        s = (s + 1 == NSTG) ? 0 : s + 1;
    }
}

// Epilogue: fused RMSNorm + NeoX RoPE (table) + fp16 convert (warp tile = one head)
__device__ __forceinline__ void epi_norm_rope(
    float acc[2][8][4], const int* __restrict__ rows,
    const float* __restrict__ w, const float2* __restrict__ rope, float sc,
    fp16* __restrict__ Out, int outstride, int headcol0)
{
    const int lane = threadIdx.x & 31;
    const int wid = threadIdx.x >> 5;
    const int wm = (wid & 3) * 32;
    const int rq = lane >> 2, cq = lane & 3;

#pragma unroll
    for (int mi = 0; mi < 2; mi++) {
#pragma unroll
        for (int hf = 0; hf < 2; hf++) {
            int r = wm + mi * 16 + rq + hf * 8;
            int gr = rows[r];
            float ss = 0.f;
#pragma unroll
            for (int nf = 0; nf < 8; nf++) {
                float a = acc[mi][nf][hf * 2], b = acc[mi][nf][hf * 2 + 1];
                ss += a * a + b * b;
            }
            ss += __shfl_xor_sync(0xffffffff, ss, 1);
            ss += __shfl_xor_sync(0xffffffff, ss, 2);
            float rn = rsqrtf(ss * (1.0f / 64.0f) + 1e-6f) * sc;
            const float2* rt = rope + (size_t)gr * 32;
#pragma unroll
            for (int nf = 0; nf < 4; nf++) {
                float o1[2], o2[2];
#pragma unroll
                for (int par = 0; par < 2; par++) {
                    int c = nf * 8 + cq * 2 + par;
                    float y1 = acc[mi][nf][hf * 2 + par] * rn * w[c];
                    float y2 = acc[mi][nf + 4][hf * 2 + par] * rn * w[c + 32];
                    float2 cs = rt[c];
                    o1[par] = y1 * cs.x - y2 * cs.y;
                    o2[par] = y2 * cs.x + y1 * cs.y;
                }
                size_t base = (size_t)gr * outstride + headcol0 + nf * 8 + cq * 2;
                *reinterpret_cast<uint32_t*>(Out + base) = pack_half2(o1[0], o1[1]);
                *reinterpret_cast<uint32_t*>(Out + base + 32) = pack_half2(o2[0], o2[1]);
            }
        }
    }
}

// Epilogue: plain fp16 convert (v)
__device__ __forceinline__ void epi_conv(
    float acc[2][8][4], const int* __restrict__ rows,
    fp16* __restrict__ Out, int outstride, int col0)
{
    const int lane = threadIdx.x & 31;
    const int wid = threadIdx.x >> 5;
    const int wm = (wid & 3) * 32;
    const int wn = (wid >> 2) * 64;
    const int rq = lane >> 2, cq = lane & 3;
#pragma unroll
    for (int mi = 0; mi < 2; mi++) {
        int r = wm + mi * 16 + rq;
        size_t gr0 = (size_t)rows[r];
        size_t gr1 = (size_t)rows[r + 8];
#pragma unroll
        for (int nf = 0; nf < 8; nf++) {
            int col = col0 + wn + nf * 8 + cq * 2;
            *reinterpret_cast<uint32_t*>(Out + gr0 * outstride + col) =
                pack_half2(acc[mi][nf][0], acc[mi][nf][1]);
            *reinterpret_cast<uint32_t*>(Out + gr1 * outstride + col) =
                pack_half2(acc[mi][nf][2], acc[mi][nf][3]);
        }
    }
}

// Merged q-proj (bid<256, routed) + k-proj + v-proj; fused norm/rope epilogues.
__global__ void __launch_bounds__(256, 2) gemm_qkv(
    const fp16* __restrict__ h, const fp16* __restrict__ wq,
    const fp16* __restrict__ wk, const fp16* __restrict__ wv,
    const int* __restrict__ sort_idx, const float2* __restrict__ rope,
    const float* __restrict__ q_norm_w, const float* __restrict__ k_norm_w,
    fp16* __restrict__ qv, fp16* __restrict__ kv, fp16* __restrict__ vv)
{
    extern __shared__ char smc[];
    float acc[2][8][4];
    int* rows = (int*)smc;
    int bid = blockIdx.x;
    const int wn = ((threadIdx.x >> 5) >> 2) * 64;

    if (bid < 256) {
        int x = bid & 15, y = (bid >> 4) & 3, z = bid >> 6;
        gemm_mainloop(h, wq + (size_t)z * HID * DQ,
                      sort_idx, HID, DQ, y * 128, x * 128, z * CHUNK, smc, acc);
        epi_norm_rope(acc, rows, q_norm_w, rope, 0.125f, qv, DQ, x * 128 + wn);
    } else {
        int bb = bid - 256;
        int x = bb & 7, y = bb >> 3;
        if (x < 4) {
            gemm_mainloop(h, wk, nullptr, HID, DKV, y * 128, x * 128, 0, smc, acc);
            epi_norm_rope(acc, rows, k_norm_w, rope, 1.0f, kv, DKV, x * 128 + wn);
        } else {
            gemm_mainloop(h, wv, nullptr, HID, DKV, y * 128, (x - 4) * 128, 0, smc, acc);
            epi_conv(acc, rows, vv, DKV, (x - 4) * 128);
        }
    }
}

// o-proj (routed), fp32 output
__global__ void __launch_bounds__(256, 2) gemm_o(
    const fp16* __restrict__ o, const fp16* __restrict__ wo,
    float* __restrict__ out, const int* __restrict__ sort_idx)
{
    extern __shared__ char smc[];
    float acc[2][8][4];
    int* rows = (int*)smc;
    int bid = blockIdx.x;
    int x = bid & 15, y = (bid >> 4) & 3, z = bid >> 6;
    gemm_mainloop(o, wo + (size_t)z * DQ * HID,
                  sort_idx, DQ, HID, y * 128, x * 128, z * CHUNK, smc, acc);

    const int lane = threadIdx.x & 31;
    const int wid = threadIdx.x >> 5;
    const int wm = (wid & 3) * 32;
    const int wn = (wid >> 2) * 64;
    const int rq = lane >> 2;
    const int cq = (lane & 3) * 2;
#pragma unroll
    for (int mi = 0; mi < 2; mi++) {
        int r = wm + mi * 16 + rq;
        size_t gr0 = (size_t)rows[r];
        size_t gr1 = (size_t)rows[r + 8];
#pragma unroll
        for (int ni = 0; ni < 8; ni++) {
            int col = x * 128 + wn + ni * 8 + cq;
            *reinterpret_cast<float2*>(&out[gr0 * HID + col]) =
                make_float2(acc[mi][ni][0], acc[mi][ni][1]);
            *reinterpret_cast<float2*>(&out[gr1 * HID + col]) =
                make_float2(acc[mi][ni][2], acc[mi][ni][3]);
        }
    }
}

// ---------------------------------------------------------------------------
// fp16 flash attention, AQ=64 / 128 threads / 3 CTAs per SM, 3-stage KV pipe.
// ---------------------------------------------------------------------------
#define AQ 64
#define AK 64
#define LDK 72
#define KSM (AK * LDK)     // 4608 elements
#define ASTG 3
#define ASMEM (2 * ASTG * KSM * 2 + ASTG * AK * 4)   // 56064

__device__ __forceinline__ void attn_issue(
    uint32_t sbase, int s, int kt, int kvh, int tid,
    const fp16* __restrict__ k_g, const fp16* __restrict__ v_g,
    const int* __restrict__ pos, int* __restrict__ kpos_sm)
{
#pragma unroll
    for (int i = 0; i < 8; i++) {
        int f = tid + i * 128;          // 0..1023
        int arr = f >> 9;               // 0=K, 1=V
        int r = (f >> 3) & 63;
        int seg = f & 7;
        const fp16* src = arr ? v_g : k_g;
        uint32_t dst = sbase + (uint32_t)((s * 2 + arr) * KSM + r * LDK) * 2
                     + seg * 16;
        CP16(dst, src + (size_t)(kt * AK + r) * DKV + (size_t)kvh * HD + seg * 8);
    }
    if (tid < AK) kpos_sm[s * AK + tid] = pos[kt * AK + tid];
    CP_COMMIT();
}

__global__ void __launch_bounds__(128, 3) attn_mma(
    const fp16* __restrict__ q_g, const fp16* __restrict__ k_g,
    const fp16* __restrict__ v_g, const int* __restrict__ pos,
    fp16* __restrict__ o_g)
{
    extern __shared__ char sm[];
    const uint32_t sbase = smem_u32(sm);
    int* kpos = (int*)(sm + (size_t)2 * ASTG * KSM * 2);

    const int tid = threadIdx.x;
    const int w = tid >> 5;
    const int l = tid & 31;
    const int qt = gridDim.x - 1 - blockIdx.x;   // heavy tiles first
    const int h = blockIdx.y;
    const int kvh = h >> 2;
    const int q0 = qt * AQ;
    const int ntile = qt + 1;

    attn_issue(sbase, 0, 0, kvh, tid, k_g, v_g, pos, kpos);
    attn_issue(sbase, 1, 1 < ntile ? 1 : 0, kvh, tid, k_g, v_g, pos, kpos);
    attn_issue(sbase, 2, 2 < ntile ? 2 : 0, kvh, tid, k_g, v_g, pos, kpos);

    const int rq = l >> 2;
    const int cq = l & 3;
    const int row0 = w * 16 + rq;

    // Q fragments straight from gmem
    uint32_t qf[4][4];
    {
        const fp16* qb = q_g + (size_t)(q0 + row0) * DQ + h * HD;
#pragma unroll
        for (int kf = 0; kf < 4; kf++) {
            int e0 = kf * 16 + cq * 2;
            qf[kf][0] = *reinterpret_cast<const uint32_t*>(qb + e0);
            qf[kf][1] = *reinterpret_cast<const uint32_t*>(qb + 8 * DQ + e0);
            qf[kf][2] = *reinterpret_cast<const uint32_t*>(qb + e0 + 8);
            qf[kf][3] = *reinterpret_cast<const uint32_t*>(qb + 8 * DQ + e0 + 8);
        }
    }
    const int qp0 = pos[q0 + row0];
    const int qp1 = pos[q0 + row0 + 8];

    float o[8][4];
#pragma unroll
    for (int nf = 0; nf < 8; nf++)
#pragma unroll
        for (int e = 0; e < 4; e++) o[nf][e] = 0.f;
    float m0 = -1e30f, m1 = -1e30f, l0 = 0.f, l1 = 0.f;

    const int lrow16 = l & 15;
    const int lsel = l >> 4;
    const uint32_t lnK = (((l >> 4) * 8 + (l & 7)) * LDK + ((l >> 3) & 1) * 8) * 2;

    int s = 0;
    for (int kt = 0; kt < ntile; kt++) {
        if (kt < ntile - 2)      CP_WAIT(2);
        else if (kt == ntile - 2) CP_WAIT(1);
        else                      CP_WAIT(0);
        __syncthreads();

        const uint32_t kb = sbase + (uint32_t)((s * 2 + 0) * KSM) * 2;
        const uint32_t vb = sbase + (uint32_t)((s * 2 + 1) * KSM) * 2;

        float sv[8][4];
#pragma unroll
        for (int nf = 0; nf < 8; nf++)
#pragma unroll
            for (int e = 0; e < 4; e++) sv[nf][e] = 0.f;

        // S = Q K^T
#pragma unroll
        for (int kf = 0; kf < 4; kf++) {
#pragma unroll
            for (int np = 0; np < 4; np++) {
                uint32_t koff = kb + (uint32_t)(np * 16 * LDK) * 2 + kf * 32 + lnK;
                uint32_t b0, b1, b2, b3;
                LDSM_4(b0, b1, b2, b3, koff);
                MMA16816(sv[2 * np], qf[kf], b0, b1);
                MMA16816(sv[2 * np + 1], qf[kf], b2, b3);
            }
        }

        if (kt == qt) {   // only diagonal tile crosses the mask
            const int* kp = kpos + s * AK;
#pragma unroll
            for (int nf = 0; nf < 8; nf++) {
                int c = nf * 8 + cq * 2;
                int k0 = kp[c], k1 = kp[c + 1];
                if (k0 > qp0) sv[nf][0] = -1e30f;
                if (k1 > qp0) sv[nf][1] = -1e30f;
                if (k0 > qp1) sv[nf][2] = -1e30f;
                if (k1 > qp1) sv[nf][3] = -1e30f;
            }
        }

        float mt0 = -1e30f, mt1 = -1e30f;
#pragma unroll
        for (int nf = 0; nf < 8; nf++) {
            mt0 = fmaxf(mt0, fmaxf(sv[nf][0], sv[nf][1]));
            mt1 = fmaxf(mt1, fmaxf(sv[nf][2], sv[nf][3]));
        }
        mt0 = fmaxf(mt0, __shfl_xor_sync(0xffffffff, mt0, 1));
        mt0 = fmaxf(mt0, __shfl_xor_sync(0xffffffff, mt0, 2));
        mt1 = fmaxf(mt1, __shfl_xor_sync(0xffffffff, mt1, 1));
        mt1 = fmaxf(mt1, __shfl_xor_sync(0xffffffff, mt1, 2));
        float mn0 = fmaxf(m0, mt0), mn1 = fmaxf(m1, mt1);
        float a0 = __expf(m0 - mn0), a1 = __expf(m1 - mn1);
        m0 = mn0; m1 = mn1;
#pragma unroll
        for (int nf = 0; nf < 8; nf++) {
            o[nf][0] *= a0; o[nf][1] *= a0;
            o[nf][2] *= a1; o[nf][3] *= a1;
        }
        float rs0 = 0.f, rs1 = 0.f;
#pragma unroll
        for (int nf = 0; nf < 8; nf++) {
            sv[nf][0] = __expf(sv[nf][0] - mn0); rs0 += sv[nf][0];
            sv[nf][1] = __expf(sv[nf][1] - mn0); rs0 += sv[nf][1];
            sv[nf][2] = __expf(sv[nf][2] - mn1); rs1 += sv[nf][2];
            sv[nf][3] = __expf(sv[nf][3] - mn1); rs1 += sv[nf][3];
        }
        rs0 += __shfl_xor_sync(0xffffffff, rs0, 1);
        rs0 += __shfl_xor_sync(0xffffffff, rs0, 2);
        rs1 += __shfl_xor_sync(0xffffffff, rs1, 1);
        rs1 += __shfl_xor_sync(0xffffffff, rs1, 2);
        l0 = l0 * a0 + rs0;
        l1 = l1 * a1 + rs1;

        // O += P V
#pragma unroll
        for (int kfk = 0; kfk < 4; kfk++) {
            uint32_t pa[4];
            pa[0] = pack_half2(sv[2 * kfk][0], sv[2 * kfk][1]);
            pa[1] = pack_half2(sv[2 * kfk][2], sv[2 * kfk][3]);
            pa[2] = pack_half2(sv[2 * kfk + 1][0], sv[2 * kfk + 1][1]);
            pa[3] = pack_half2(sv[2 * kfk + 1][2], sv[2 * kfk + 1][3]);

            uint32_t vf[8][2];
#pragma unroll
            for (int nfp = 0; nfp < 4; nfp++) {
                uint32_t off = (uint32_t)((kfk * 16 + lrow16) * LDK
                                          + nfp * 16 + lsel * 8) * 2;
                uint32_t r0, r1, r2, r3;
                LDSM_T4(r0, r1, r2, r3, vb + off);
                vf[2 * nfp][0] = r0;     vf[2 * nfp][1] = r1;
                vf[2 * nfp + 1][0] = r2; vf[2 * nfp + 1][1] = r3;
            }
#pragma unroll
            for (int nf = 0; nf < 8; nf++)
                MMA16816(o[nf], pa, vf[nf][0], vf[nf][1]);
        }

        __syncthreads();
        if (kt + ASTG < ntile)
            attn_issue(sbase, s, kt + ASTG, kvh, tid, k_g, v_g, pos, kpos);
        s = (s + 1 == ASTG) ? 0 : s + 1;
    }

    float i0 = 1.f / l0, i1 = 1.f / l1;
    int g0 = q0 + w * 16 + rq;
    int g1 = g0 + 8;
#pragma unroll
    for (int nf = 0; nf < 8; nf++) {
        int col = h * HD + nf * 8 + cq * 2;
        *reinterpret_cast<uint32_t*>(o_g + (size_t)g0 * DQ + col) =
            pack_half2(o[nf][0] * i0, o[nf][1] * i0);
        *reinterpret_cast<uint32_t*>(o_g + (size_t)g1 * DQ + col) =
            pack_half2(o[nf][2] * i1, o[nf][3] * i1);
    }
}

// ---------------------------------------------------------------------------
extern "C" void kernel_launch(void* const* d_in, const int* in_sizes, int n_in,
                              void* d_out, int out_size)
{
    const float* hidden    = (const float*)d_in[0];
    const int*   positions = (const int*)  d_in[1];
    const int*   sort_idx  = (const int*)  d_in[2];
    const float* q_proj_w  = (const float*)d_in[3];
    const float* o_proj_w  = (const float*)d_in[4];
    const float* k_w       = (const float*)d_in[5];
    const float* v_w       = (const float*)d_in[6];
    const float* q_norm_w  = (const float*)d_in[7];
    const float* k_norm_w  = (const float*)d_in[8];
    float* out = (float*)d_out;

    fp16 *h, *o, *qv, *kv, *vv, *wq, *wo, *wk, *wv;
    float2* rope;
    cudaGetSymbolAddress((void**)&h, g_h);
    cudaGetSymbolAddress((void**)&o, g_o);
    cudaGetSymbolAddress((void**)&qv, g_qv);
    cudaGetSymbolAddress((void**)&kv, g_kv);
    cudaGetSymbolAddress((void**)&vv, g_vv);
    cudaGetSymbolAddress((void**)&wq, g_wq);
    cudaGetSymbolAddress((void**)&wo, g_wo);
    cudaGetSymbolAddress((void**)&wk, g_wk);
    cudaGetSymbolAddress((void**)&wv, g_wv);
    cudaGetSymbolAddress((void**)&rope, g_rope);

    cudaFuncSetAttribute(gemm_qkv, cudaFuncAttributeMaxDynamicSharedMemorySize, GEMM_SMEM);
    cudaFuncSetAttribute(gemm_o, cudaFuncAttributeMaxDynamicSharedMemorySize, GEMM_SMEM);
    cudaFuncSetAttribute(attn_mma, cudaFuncAttributeMaxDynamicSharedMemorySize, ASMEM);

    // 1) coalesced fp32->fp16 converts + RoPE table
    prep_split<<<PREP_BLOCKS, 256>>>(
        q_proj_w, o_proj_w, k_w, v_w, hidden, positions,
        wq, wo, wk, wv, h, rope);

    // 2) q/k/v projections with fused RMSNorm/RoPE epilogues
    gemm_qkv<<<384, 256, GEMM_SMEM>>>(
        h, wq, wk, wv, sort_idx, rope, q_norm_w, k_norm_w, qv, kv, vv);

    // 3) flash attention (3-stage KV pipeline)
    attn_mma<<<dim3(NTOK / AQ, NH), 128, ASMEM>>>(qv, kv, vv, positions, o);

    // 4) o-proj (routed)
    gemm_o<<<256, 256, GEMM_SMEM>>>(o, wo, out, sort_idx);
}